// round 9
// baseline (speedup 1.0000x reference)
#include <cuda_runtime.h>
#include <cuda_bf16.h>
#include <cstdint>

#define EPS_F 1e-5f

__device__ float g_v2[67108864];      // (B*M, 1024) v2 after celu+GN
__device__ float g_kq[67108864];      // (B*M, 1024) GN(celu(k)) * q
__device__ __nv_bfloat16 g_xhi[67108864];   // X split hi (row-major)
__device__ __nv_bfloat16 g_xlo[67108864];   // X split lo
__device__ __nv_bfloat16 g_wthi[1048576];   // W^T split hi  [n][k]
__device__ __nv_bfloat16 g_wtlo[1048576];   // W^T split lo  [n][k]
__device__ float g_qgn[65536];
__device__ float g_v1gn[65536];
__device__ float g_qv1pre[131072];
__device__ float g_logits[524288];    // (B, H, M)
__device__ float g_ampool[32768];     // (B, H, 64)

// ---------------- helpers ----------------
__device__ __forceinline__ uint32_t smem_to_u32(const void* p) {
    uint32_t a;
    asm("{ .reg .u64 t; cvta.to.shared.u64 t, %1; cvt.u32.u64 %0, t; }" : "=r"(a) : "l"(p));
    return a;
}
__device__ __forceinline__ float celu_f(float x) {
    return x > 0.f ? x : 1.3f * expm1f(x * (1.0f / 1.3f));
}
__device__ __forceinline__ void cvt_split2(float a, float b, uint32_t& hi, uint32_t& lo) {
    __nv_bfloat16 ha = __float2bfloat16(a);
    __nv_bfloat16 hb = __float2bfloat16(b);
    __nv_bfloat16 la = __float2bfloat16(a - __bfloat162float(ha));
    __nv_bfloat16 lb = __float2bfloat16(b - __bfloat162float(hb));
    __nv_bfloat162 h2(ha, hb), l2(la, lb);
    hi = *reinterpret_cast<uint32_t*>(&h2);
    lo = *reinterpret_cast<uint32_t*>(&l2);
}
__device__ __forceinline__ void ldsm4(uint32_t* r, uint32_t addr) {
    asm volatile("ldmatrix.sync.aligned.m8n8.x4.shared.b16 {%0,%1,%2,%3}, [%4];"
                 : "=r"(r[0]), "=r"(r[1]), "=r"(r[2]), "=r"(r[3]) : "r"(addr));
}
__device__ __forceinline__ void mma16816(float* d, const uint32_t* a,
                                         const uint32_t b0, const uint32_t b1) {
    asm volatile(
        "mma.sync.aligned.m16n8k16.row.col.f32.bf16.bf16.f32 "
        "{%0,%1,%2,%3}, {%4,%5,%6,%7}, {%8,%9}, {%0,%1,%2,%3};"
        : "+f"(d[0]), "+f"(d[1]), "+f"(d[2]), "+f"(d[3])
        : "r"(a[0]), "r"(a[1]), "r"(a[2]), "r"(a[3]), "r"(b0), "r"(b1));
}
__device__ __forceinline__ void cp16(uint32_t dst, const void* src) {
    asm volatile("cp.async.cg.shared.global [%0], [%1], 16;" :: "r"(dst), "l"(src) : "memory");
}

// ---------------- zero scratch ----------------
__global__ void zero_kernel() {
    int i = blockIdx.x * 256 + threadIdx.x;
    if (i < 32768)  g_ampool[i] = 0.f;
    if (i < 131072) g_qv1pre[i] = 0.f;
}

// ---------------- split passes ----------------
__global__ void split_x(const float* __restrict__ X) {
    size_t i = ((size_t)blockIdx.x * 256 + threadIdx.x) * 4;
    float4 v = *(const float4*)(X + i);
    uint32_t h0, l0, h1, l1;
    cvt_split2(v.x, v.y, h0, l0);
    cvt_split2(v.z, v.w, h1, l1);
    *(uint2*)(g_xhi + i) = make_uint2(h0, h1);
    *(uint2*)(g_xlo + i) = make_uint2(l0, l1);
}

// transpose + split: W[k][n] -> g_wthi/lo[n][k]
__global__ void split_w(const float* __restrict__ W) {
    __shared__ float tile[32][33];
    const int kt = blockIdx.x * 32, nt = blockIdx.y * 32;
    const int tx = threadIdx.x & 31, ty = threadIdx.x >> 5;   // 256 thr
#pragma unroll
    for (int j = 0; j < 4; j++)
        tile[ty + j * 8][tx] = W[(size_t)(kt + ty + j * 8) * 1024 + nt + tx];
    __syncthreads();
#pragma unroll
    for (int j = 0; j < 4; j++) {
        const int n = nt + ty + j * 8, k = kt + tx;
        float v = tile[tx][ty + j * 8];
        __nv_bfloat16 h = __float2bfloat16(v);
        __nv_bfloat16 l = __float2bfloat16(v - __bfloat162float(h));
        g_wthi[(size_t)n * 1024 + k] = h;
        g_wtlo[(size_t)n * 1024 + k] = l;
    }
}

// ---------------- small branches (q, v1) ----------------
__global__ void small_partial(const float* __restrict__ query,
                              const float* __restrict__ value1,
                              const float* __restrict__ Wq,
                              const float* __restrict__ Wv1) {
    const int g = blockIdx.x, kc = blockIdx.y, z = blockIdx.z;
    const float* X = z ? value1 : query;
    const float* W = z ? Wv1 : Wq;
    __shared__ float Xs[16 * 64];
    __shared__ float Ws[16 * 128];
    const int tid = threadIdx.x;
    const int ty = tid >> 4, tx = tid & 15;
    const int n0 = g << 7;
    const int lm = tid >> 2, lk = (tid & 3) << 2;
    const int lk2 = tid >> 4, ln = (tid & 15) << 3;

    float acc[4][8];
#pragma unroll
    for (int i = 0; i < 4; i++)
#pragma unroll
        for (int j = 0; j < 8; j++) acc[i][j] = 0.f;

    const int kbeg = kc * 256, kend = kbeg + 256;
    for (int k0 = kbeg; k0 < kend; k0 += 16) {
        float4 xv = *(const float4*)(X + (size_t)lm * 1024 + k0 + lk);
        float4 w0 = *(const float4*)(W + (size_t)(k0 + lk2) * 1024 + n0 + ln);
        float4 w1 = *(const float4*)(W + (size_t)(k0 + lk2) * 1024 + n0 + ln + 4);
        __syncthreads();
        Xs[(lk + 0) * 64 + lm] = xv.x;
        Xs[(lk + 1) * 64 + lm] = xv.y;
        Xs[(lk + 2) * 64 + lm] = xv.z;
        Xs[(lk + 3) * 64 + lm] = xv.w;
        *(float4*)(Ws + lk2 * 128 + ln) = w0;
        *(float4*)(Ws + lk2 * 128 + ln + 4) = w1;
        __syncthreads();
#pragma unroll
        for (int kk = 0; kk < 16; kk++) {
            float4 a = *(const float4*)(Xs + kk * 64 + (ty << 2));
            float4 b0 = *(const float4*)(Ws + kk * 128 + (tx << 3));
            float4 b1 = *(const float4*)(Ws + kk * 128 + (tx << 3) + 4);
            float av[4] = {a.x, a.y, a.z, a.w};
            float bv[8] = {b0.x, b0.y, b0.z, b0.w, b1.x, b1.y, b1.z, b1.w};
#pragma unroll
            for (int i = 0; i < 4; i++)
#pragma unroll
                for (int j = 0; j < 8; j++) acc[i][j] += av[i] * bv[j];
        }
    }
    float* dst = g_qv1pre + z * 65536;
#pragma unroll
    for (int i = 0; i < 4; i++)
#pragma unroll
        for (int j = 0; j < 8; j++)
            atomicAdd(&dst[((ty << 2) + i) * 1024 + n0 + (tx << 3) + j], acc[i][j]);
}

__global__ void small_finalize(const float* __restrict__ bq, const float* __restrict__ gq,
                               const float* __restrict__ gbq,
                               const float* __restrict__ bv1, const float* __restrict__ gv1,
                               const float* __restrict__ gbv1) {
    const int row = blockIdx.x;
    const int z = row >> 6, r = row & 63;
    const int tid = threadIdx.x;
    const float* pre = g_qv1pre + z * 65536 + r * 1024;
    const float* bias = z ? bv1 : bq;
    const float* gam  = z ? gv1 : gq;
    const float* bet  = z ? gbv1 : gbq;
    float v[4], s = 0.f, s2 = 0.f;
#pragma unroll
    for (int j = 0; j < 4; j++) {
        int c = tid * 4 + j;
        float x = celu_f(pre[c] + bias[c]);
        v[j] = x; s += x; s2 += x * x;
    }
#pragma unroll
    for (int o = 16; o; o >>= 1) {
        s  += __shfl_xor_sync(0xffffffffu, s, o);
        s2 += __shfl_xor_sync(0xffffffffu, s2, o);
    }
    float mu = s * (1.f / 128.f);
    float var = s2 * (1.f / 128.f) - mu * mu;
    float rs = rsqrtf(var + EPS_F);
    float* o = z ? g_v1gn : g_qgn;
#pragma unroll
    for (int j = 0; j < 4; j++) {
        int c = tid * 4 + j;
        o[r * 1024 + c] = (v[j] - mu) * rs * gam[c] + bet[c];
    }
}

// ---------------------------------------------------------------------------
// mma.sync GEMM on pre-split bf16, cp.async 3-stage pipeline.
// D[128x128] = X[128 x 1024] @ W[1024 x 128] via hihi+hilo+lohi.
// Sources: g_xhi/g_xlo (row-major), g_wthi/g_wtlo ([n][k]).
// grid 4096 (512 m x 8 n), 256 thr (8 warps, 2m x 4n).
// smem: 3 stages x 40960B  (Ahi 10240 | Alo 10240 | Bhi 10240 | Blo 10240;
//       row pitch 80B, 128 rows); C epilogue aliases stage bufs; qS at end.
// ---------------------------------------------------------------------------
#define STG_B 40960
#define SMQ_OFF (3 * STG_B)
#define SM_GEMM_TOTAL (SMQ_OFF + 512)

template <bool QMUL>
__global__ void __launch_bounds__(256, 1)
gemm_kernel(const float* __restrict__ bias, const float* __restrict__ gam,
            const float* __restrict__ bet) {
    extern __shared__ char smem[];
    const uint32_t su = smem_to_u32(smem);
    const int tid = threadIdx.x, lane = tid & 31, wid = tid >> 5;
    const int mwarp = wid >> 2, nwarp = wid & 3;
    const int r0 = (int)(blockIdx.x >> 3) * 128;
    const int n0 = (int)(blockIdx.x & 7) * 128;
    const int b = r0 >> 10;

    float* qS = (float*)(smem + SMQ_OFF);
    if (QMUL && tid < 128) qS[tid] = g_qgn[b * 1024 + n0 + tid];

    const int rowL = (lane & 7) + ((lane >> 3) & 1) * 8;
    const int kL8 = (lane >> 4) * 8;
    const uint32_t lmoff = (uint32_t)(rowL * 80 + kL8 * 2);

    // staging: thread -> (row, 2x16B segs); 8 cp.async per stage
    const int srow = tid >> 1, sseg = (tid & 1) * 2;
    const __nv_bfloat16* Axh = g_xhi + (size_t)(r0 + srow) * 1024 + sseg * 8;
    const __nv_bfloat16* Axl = g_xlo + (size_t)(r0 + srow) * 1024 + sseg * 8;
    const __nv_bfloat16* Bwh = g_wthi + (size_t)(n0 + srow) * 1024 + sseg * 8;
    const __nv_bfloat16* Bwl = g_wtlo + (size_t)(n0 + srow) * 1024 + sseg * 8;
    const uint32_t dA = su + srow * 80 + sseg * 16;

#define STAGE(s, c) do { \
    if ((c) < 32) { \
        const int _k0 = (c) << 5; \
        const uint32_t _d = dA + (s) * STG_B; \
        cp16(_d,               Axh + _k0);      cp16(_d + 16,               Axh + _k0 + 8); \
        cp16(_d + 10240,       Axl + _k0);      cp16(_d + 10240 + 16,       Axl + _k0 + 8); \
        cp16(_d + 20480,       Bwh + _k0);      cp16(_d + 20480 + 16,       Bwh + _k0 + 8); \
        cp16(_d + 30720,       Bwl + _k0);      cp16(_d + 30720 + 16,       Bwl + _k0 + 8); \
    } \
    asm volatile("cp.async.commit_group;" ::: "memory"); \
} while (0)

    float d[4][4][4];
#pragma unroll
    for (int i = 0; i < 4; i++)
#pragma unroll
        for (int j = 0; j < 4; j++)
#pragma unroll
            for (int u = 0; u < 4; u++) d[i][j][u] = 0.f;

    STAGE(0, 0);
    STAGE(1, 1);

    for (int t = 0; t < 32; t++) {
        asm volatile("cp.async.wait_group 1;" ::: "memory");
        __syncthreads();
        STAGE((t + 2) % 3, t + 2);

        const uint32_t abase = su + (t % 3) * STG_B +
                               (uint32_t)(mwarp * 64 * 80) + lmoff;
        const uint32_t bbase = su + (t % 3) * STG_B + 20480 +
                               (uint32_t)(nwarp * 32 * 80) + lmoff;
#pragma unroll
        for (int sl = 0; sl < 2; sl++) {
            uint32_t Ah[4][4], Al[4][4], Bh[4][2], Bl[4][2];
#pragma unroll
            for (int fm = 0; fm < 4; fm++) {
                ldsm4(Ah[fm], abase + fm * (16 * 80) + sl * 32);
                ldsm4(Al[fm], abase + 10240 + fm * (16 * 80) + sl * 32);
            }
#pragma unroll
            for (int g = 0; g < 2; g++) {
                uint32_t tm[4];
                ldsm4(tm, bbase + g * (16 * 80) + sl * 32);
                Bh[2 * g][0] = tm[0]; Bh[2 * g][1] = tm[2];
                Bh[2 * g + 1][0] = tm[1]; Bh[2 * g + 1][1] = tm[3];
                ldsm4(tm, bbase + 10240 + g * (16 * 80) + sl * 32);
                Bl[2 * g][0] = tm[0]; Bl[2 * g][1] = tm[2];
                Bl[2 * g + 1][0] = tm[1]; Bl[2 * g + 1][1] = tm[3];
            }
#pragma unroll
            for (int fm = 0; fm < 4; fm++)
#pragma unroll
                for (int fn = 0; fn < 4; fn++) {
                    mma16816(d[fm][fn], Ah[fm], Bh[fn][0], Bh[fn][1]);
                    mma16816(d[fm][fn], Ah[fm], Bl[fn][0], Bl[fn][1]);
                    mma16816(d[fm][fn], Al[fm], Bh[fn][0], Bh[fn][1]);
                }
        }
        __syncthreads();
    }

    // ---- epilogue: frags -> smem (aliases stage bufs), per-row celu+GN ----
    float* Cs = (float*)smem;
    {
        const int mb = mwarp * 64, nb = nwarp * 32;
        const int r = lane >> 2, c = (lane & 3) * 2;
#pragma unroll
        for (int fm = 0; fm < 4; fm++)
#pragma unroll
            for (int fn = 0; fn < 4; fn++) {
                const int rr = mb + fm * 16 + r;
                const int cc = nb + fn * 8 + c;
                *(float2*)&Cs[rr * 132 + cc] = make_float2(d[fm][fn][0], d[fm][fn][1]);
                *(float2*)&Cs[(rr + 8) * 132 + cc] = make_float2(d[fm][fn][2], d[fm][fn][3]);
            }
    }
    __syncthreads();
    {
        const int row = tid >> 1, half = tid & 1;
        const int c0 = half * 64;
        float v[64];
        float s = 0.f, s2 = 0.f;
#pragma unroll
        for (int j = 0; j < 16; j++) {
            float4 x4 = *(const float4*)&Cs[row * 132 + c0 + j * 4];
            float* px = (float*)&x4;
#pragma unroll
            for (int u = 0; u < 4; u++) {
                float x = celu_f(px[u] + __ldg(&bias[n0 + c0 + j * 4 + u]));
                v[j * 4 + u] = x; s += x; s2 += x * x;
            }
        }
        s  += __shfl_xor_sync(0xffffffffu, s, 1);
        s2 += __shfl_xor_sync(0xffffffffu, s2, 1);
        const float mu = s * (1.f / 128.f);
        const float rs = rsqrtf(s2 * (1.f / 128.f) - mu * mu + EPS_F);
        float* outp = (QMUL ? g_kq : g_v2) + (size_t)(r0 + row) * 1024 + n0 + c0;
#pragma unroll
        for (int j = 0; j < 16; j++) {
            float4 o;
            float* po = (float*)&o;
#pragma unroll
            for (int u = 0; u < 4; u++) {
                const int ch = n0 + c0 + j * 4 + u;
                float xn = (v[j * 4 + u] - mu) * rs * __ldg(&gam[ch]) + __ldg(&bet[ch]);
                if (QMUL) xn *= qS[c0 + j * 4 + u];
                po[u] = xn;
            }
            *(float4*)(outp + j * 4) = o;
        }
    }
#undef STAGE
}

// ---------------------------------------------------------------------------
// attn: am = relu(g_kq @ Wb + bb); logits = am@Wl+bl; ampool partials.
// ---------------------------------------------------------------------------
__global__ void __launch_bounds__(256, 2)
attn_kernel(const float* __restrict__ Wb, const float* __restrict__ bb,
            const float* __restrict__ Wl, const float* __restrict__ bl,
            const float* __restrict__ mask) {
    __shared__ float WbS[8192];
    __shared__ float WlS[64], bbS[64], mS[64], apS[64];
    const int tid = threadIdx.x;
    const int ty = tid >> 4, tx = tid & 15;
    const int r0 = blockIdx.x << 6;
    const int b = r0 >> 10, mbase = r0 & 1023;

    for (int i = tid; i < 8192; i += 256) WbS[i] = Wb[i];
    if (tid < 64) {
        WlS[tid] = Wl[tid];
        bbS[tid] = bb[tid];
        mS[tid] = mask[r0 + tid];
    }
    __syncthreads();

    for (int g = 0; g < 8; ++g) {
        if (tid < 64) apS[tid] = 0.f;
        __syncthreads();

        float am[4][4];
#pragma unroll
        for (int i = 0; i < 4; i++)
#pragma unroll
            for (int j = 0; j < 4; j++) am[i][j] = 0.f;

        const float* sp = g_kq + (size_t)r0 * 1024 + (g << 7);
        for (int k4 = 0; k4 < 128; k4 += 4) {
            float4 av[4];
#pragma unroll
            for (int i = 0; i < 4; i++)
                av[i] = *(const float4*)(sp + (size_t)((ty << 2) + i) * 1024 + k4);
            float4 b0 = *(const float4*)(WbS + (k4 + 0) * 64 + (tx << 2));
            float4 b1 = *(const float4*)(WbS + (k4 + 1) * 64 + (tx << 2));
            float4 b2 = *(const float4*)(WbS + (k4 + 2) * 64 + (tx << 2));
            float4 b3 = *(const float4*)(WbS + (k4 + 3) * 64 + (tx << 2));
#pragma unroll
            for (int i = 0; i < 4; i++) {
                am[i][0] += av[i].x * b0.x; am[i][1] += av[i].x * b0.y;
                am[i][2] += av[i].x * b0.z; am[i][3] += av[i].x * b0.w;
                am[i][0] += av[i].y * b1.x; am[i][1] += av[i].y * b1.y;
                am[i][2] += av[i].y * b1.z; am[i][3] += av[i].y * b1.w;
                am[i][0] += av[i].z * b2.x; am[i][1] += av[i].z * b2.y;
                am[i][2] += av[i].z * b2.z; am[i][3] += av[i].z * b2.w;
                am[i][0] += av[i].w * b3.x; am[i][1] += av[i].w * b3.y;
                am[i][2] += av[i].w * b3.z; am[i][3] += av[i].w * b3.w;
            }
        }

        float lp[4];
#pragma unroll
        for (int i = 0; i < 4; i++) {
            float t = 0.f;
#pragma unroll
            for (int j = 0; j < 4; j++) {
                float a = fmaxf(am[i][j] + bbS[(tx << 2) + j], 0.f);
                am[i][j] = a;
                t += a * WlS[(tx << 2) + j];
            }
            lp[i] = t;
        }
#pragma unroll
        for (int o = 8; o; o >>= 1)
#pragma unroll
            for (int i = 0; i < 4; i++) lp[i] += __shfl_xor_sync(0xffffffffu, lp[i], o);
        if (tx == 0) {
            const float blv = __ldg(&bl[0]);
#pragma unroll
            for (int i = 0; i < 4; i++)
                g_logits[(((b << 3) + g) << 10) + mbase + (ty << 2) + i] = lp[i] + blv;
        }
#pragma unroll
        for (int j = 0; j < 4; j++) {
            float ap = am[0][j] * mS[(ty << 2) + 0] + am[1][j] * mS[(ty << 2) + 1] +
                       am[2][j] * mS[(ty << 2) + 2] + am[3][j] * mS[(ty << 2) + 3];
            atomicAdd(&apS[(tx << 2) + j], ap);
        }
        __syncthreads();
        if (tid < 64)
            atomicAdd(&g_ampool[(((b << 3) + g) << 6) + tid], apS[tid]);
        __syncthreads();
    }
}

// ---------------- finalize ----------------
__global__ void final_kernel(const float* __restrict__ mask,
                             const float* __restrict__ Wl2,
                             const float* __restrict__ bl2,
                             float* __restrict__ out) {
    const int h = blockIdx.x, b = blockIdx.y;
    const int tid = threadIdx.x;
    const int lane = tid & 31, wrp = tid >> 5;
    __shared__ float wsm[1024];
    __shared__ float redA[8], redB[8], bc[4];
    __shared__ float pm[64], ac[128], psm[256];

    const float* lg = g_logits + (((size_t)b * 8 + h) << 10);
    const float* mrow = mask + ((size_t)b << 10);

    float l[4], mk[4];
    float lmax = -1e30f, msum = 0.f;
#pragma unroll
    for (int k = 0; k < 4; k++) {
        int m = tid + (k << 8);
        mk[k] = mrow[m];
        l[k] = (mk[k] == 0.f) ? -1e9f : lg[m];
        lmax = fmaxf(lmax, l[k]);
        msum += mk[k];
    }
#pragma unroll
    for (int o = 16; o; o >>= 1) {
        lmax = fmaxf(lmax, __shfl_xor_sync(0xffffffffu, lmax, o));
        msum += __shfl_xor_sync(0xffffffffu, msum, o);
    }
    if (lane == 0) { redA[wrp] = lmax; redB[wrp] = msum; }
    __syncthreads();
    if (tid == 0) {
        float a = -1e30f, s = 0.f;
#pragma unroll
        for (int i = 0; i < 8; i++) { a = fmaxf(a, redA[i]); s += redB[i]; }
        bc[0] = a; bc[1] = s;
    }
    __syncthreads();
    const float gmax = bc[0], msumv = bc[1];

    float es = 0.f;
#pragma unroll
    for (int k = 0; k < 4; k++) {
        float e = __expf(l[k] - gmax);
        wsm[tid + (k << 8)] = e;
        es += e;
    }
#pragma unroll
    for (int o = 16; o; o >>= 1) es += __shfl_xor_sync(0xffffffffu, es, o);
    if (lane == 0) redA[wrp] = es;
    __syncthreads();
    if (tid == 0) {
        float s = 0.f;
#pragma unroll
        for (int i = 0; i < 8; i++) s += redA[i];
        bc[2] = s;
    }
    if (tid < 64) pm[tid] = g_ampool[(((b << 3) + h) << 6) + tid] / msumv;
    __syncthreads();
    const float inv = 1.f / bc[2];

    if (tid < 128) {
        float t = bl2[tid];
#pragma unroll 8
        for (int n = 0; n < 64; n++) t += pm[n] * Wl2[n * 128 + tid];
        ac[tid] = 1.f / (1.f + __expf(-t));
    }
    __syncthreads();

    const int s2 = tid >> 7, d = tid & 127;
    const float* v2p = g_v2 + ((size_t)(b << 10)) * 1024 + (h << 7) + d;
    float accp = 0.f;
    for (int m = s2; m < 1024; m += 8) {
        accp += wsm[m] * v2p[(size_t)m * 1024];
        accp += wsm[m + 2] * v2p[(size_t)(m + 2) * 1024];
        accp += wsm[m + 4] * v2p[(size_t)(m + 4) * 1024];
        accp += wsm[m + 6] * v2p[(size_t)(m + 6) * 1024];
    }
    psm[tid] = accp;
    __syncthreads();
    if (tid < 128) {
        float p = (psm[tid] + psm[tid + 128]) * inv;
        int oi = (b << 10) + (h << 7) + tid;
        out[oi] = g_v1gn[oi] * p * ac[tid];
    }
}

// ---------------- launch ----------------
extern "C" void kernel_launch(void* const* d_in, const int* in_sizes, int n_in,
                              void* d_out, int out_size) {
    const float* query  = (const float*)d_in[0];
    const float* key    = (const float*)d_in[1];
    const float* mask   = (const float*)d_in[2];
    const float* value1 = (const float*)d_in[3];
    const float* value2 = (const float*)d_in[4];
    const float* Wq  = (const float*)d_in[5];
    const float* bq  = (const float*)d_in[6];
    const float* gq  = (const float*)d_in[7];
    const float* gbq = (const float*)d_in[8];
    const float* Wk  = (const float*)d_in[9];
    const float* bk  = (const float*)d_in[10];
    const float* gk  = (const float*)d_in[11];
    const float* gbk = (const float*)d_in[12];
    const float* Wv1  = (const float*)d_in[13];
    const float* bv1  = (const float*)d_in[14];
    const float* gv1  = (const float*)d_in[15];
    const float* gbv1 = (const float*)d_in[16];
    const float* Wv2  = (const float*)d_in[17];
    const float* bv2  = (const float*)d_in[18];
    const float* gv2  = (const float*)d_in[19];
    const float* gbv2 = (const float*)d_in[20];
    const float* Wb  = (const float*)d_in[21];
    const float* bb  = (const float*)d_in[22];
    const float* Wl  = (const float*)d_in[23];
    const float* bl  = (const float*)d_in[24];
    const float* Wl2 = (const float*)d_in[25];
    const float* bl2 = (const float*)d_in[26];
    float* out = (float*)d_out;

    cudaFuncSetAttribute(gemm_kernel<true>,  cudaFuncAttributeMaxDynamicSharedMemorySize,
                         SM_GEMM_TOTAL);
    cudaFuncSetAttribute(gemm_kernel<false>, cudaFuncAttributeMaxDynamicSharedMemorySize,
                         SM_GEMM_TOTAL);

    zero_kernel<<<512, 256>>>();
    small_partial<<<dim3(8, 4, 2), 256>>>(query, value1, Wq, Wv1);
    small_finalize<<<128, 256>>>(bq, gq, gbq, bv1, gv1, gbv1);

    // k branch
    split_x<<<65536, 256>>>(key);
    split_w<<<dim3(32, 32), 256>>>(Wk);
    gemm_kernel<true><<<4096, 256, SM_GEMM_TOTAL>>>(bk, gk, gbk);

    // v2 branch (reuses split buffers)
    split_x<<<65536, 256>>>(value2);
    split_w<<<dim3(32, 32), 256>>>(Wv2);
    gemm_kernel<false><<<4096, 256, SM_GEMM_TOTAL>>>(bv2, gv2, gbv2);

    attn_kernel<<<1024, 256>>>(Wb, bb, Wl, bl, mask);
    final_kernel<<<dim3(8, 64), 256>>>(mask, Wl2, bl2, out);
}

// round 12
// speedup vs baseline: 1.0750x; 1.0750x over previous
#include <cuda_runtime.h>
#include <cuda_bf16.h>
#include <cstdint>

#define EPS_F 1e-5f

__device__ float g_v2[67108864];      // (B*M, 1024) v2 after celu+GN
__device__ float g_kq[67108864];      // (B*M, 1024) GN(celu(k)) * q
__device__ __nv_bfloat16 g_xhi[67108864];   // X split hi (row-major)
__device__ __nv_bfloat16 g_xlo[67108864];   // X split lo
__device__ __nv_bfloat16 g_wthi[1048576];   // W^T split hi  [n][k]
__device__ __nv_bfloat16 g_wtlo[1048576];   // W^T split lo  [n][k]
__device__ float g_qgn[65536];
__device__ float g_v1gn[65536];
__device__ float g_qv1pre[131072];
__device__ float g_logits[524288];    // (B, H, M)
__device__ float g_ampool[32768];     // (B, H, 64)

// ---------------- helpers ----------------
__device__ __forceinline__ uint32_t smem_to_u32(const void* p) {
    uint32_t a;
    asm("{ .reg .u64 t; cvta.to.shared.u64 t, %1; cvt.u32.u64 %0, t; }" : "=r"(a) : "l"(p));
    return a;
}
__device__ __forceinline__ float celu_f(float x) {
    return x > 0.f ? x : 1.3f * expm1f(x * (1.0f / 1.3f));
}
__device__ __forceinline__ void cvt_split2(float a, float b, uint32_t& hi, uint32_t& lo) {
    __nv_bfloat16 ha = __float2bfloat16(a);
    __nv_bfloat16 hb = __float2bfloat16(b);
    __nv_bfloat16 la = __float2bfloat16(a - __bfloat162float(ha));
    __nv_bfloat16 lb = __float2bfloat16(b - __bfloat162float(hb));
    __nv_bfloat162 h2(ha, hb), l2(la, lb);
    hi = *reinterpret_cast<uint32_t*>(&h2);
    lo = *reinterpret_cast<uint32_t*>(&l2);
}
__device__ __forceinline__ void ldsm4(uint32_t* r, uint32_t addr) {
    asm volatile("ldmatrix.sync.aligned.m8n8.x4.shared.b16 {%0,%1,%2,%3}, [%4];"
                 : "=r"(r[0]), "=r"(r[1]), "=r"(r[2]), "=r"(r[3]) : "r"(addr));
}
__device__ __forceinline__ void mma16816(float* d, const uint32_t* a,
                                         const uint32_t b0, const uint32_t b1) {
    asm volatile(
        "mma.sync.aligned.m16n8k16.row.col.f32.bf16.bf16.f32 "
        "{%0,%1,%2,%3}, {%4,%5,%6,%7}, {%8,%9}, {%0,%1,%2,%3};"
        : "+f"(d[0]), "+f"(d[1]), "+f"(d[2]), "+f"(d[3])
        : "r"(a[0]), "r"(a[1]), "r"(a[2]), "r"(a[3]), "r"(b0), "r"(b1));
}
__device__ __forceinline__ void cp16(uint32_t dst, const void* src) {
    asm volatile("cp.async.cg.shared.global [%0], [%1], 16;" :: "r"(dst), "l"(src) : "memory");
}

// ---------------- zero scratch ----------------
__global__ void zero_kernel() {
    int i = blockIdx.x * 256 + threadIdx.x;
    if (i < 32768)  g_ampool[i] = 0.f;
    if (i < 131072) g_qv1pre[i] = 0.f;
}

// ---------------- split passes ----------------
__global__ void split_x(const float* __restrict__ X) {
    size_t i = ((size_t)blockIdx.x * 256 + threadIdx.x) * 4;
    float4 v = *(const float4*)(X + i);
    uint32_t h0, l0, h1, l1;
    cvt_split2(v.x, v.y, h0, l0);
    cvt_split2(v.z, v.w, h1, l1);
    *(uint2*)(g_xhi + i) = make_uint2(h0, h1);
    *(uint2*)(g_xlo + i) = make_uint2(l0, l1);
}

// transpose + split: W[k][n] -> g_wthi/lo[n][k]
__global__ void split_w(const float* __restrict__ W) {
    __shared__ float tile[32][33];
    const int kt = blockIdx.x * 32, nt = blockIdx.y * 32;
    const int tx = threadIdx.x & 31, ty = threadIdx.x >> 5;   // 256 thr
#pragma unroll
    for (int j = 0; j < 4; j++)
        tile[ty + j * 8][tx] = W[(size_t)(kt + ty + j * 8) * 1024 + nt + tx];
    __syncthreads();
#pragma unroll
    for (int j = 0; j < 4; j++) {
        const int n = nt + ty + j * 8, k = kt + tx;
        float v = tile[tx][ty + j * 8];
        __nv_bfloat16 h = __float2bfloat16(v);
        __nv_bfloat16 l = __float2bfloat16(v - __bfloat162float(h));
        g_wthi[(size_t)n * 1024 + k] = h;
        g_wtlo[(size_t)n * 1024 + k] = l;
    }
}

// ---------------- small branches (q, v1) ----------------
__global__ void small_partial(const float* __restrict__ query,
                              const float* __restrict__ value1,
                              const float* __restrict__ Wq,
                              const float* __restrict__ Wv1) {
    const int g = blockIdx.x, kc = blockIdx.y, z = blockIdx.z;
    const float* X = z ? value1 : query;
    const float* W = z ? Wv1 : Wq;
    __shared__ float Xs[16 * 64];
    __shared__ float Ws[16 * 128];
    const int tid = threadIdx.x;
    const int ty = tid >> 4, tx = tid & 15;
    const int n0 = g << 7;
    const int lm = tid >> 2, lk = (tid & 3) << 2;
    const int lk2 = tid >> 4, ln = (tid & 15) << 3;

    float acc[4][8];
#pragma unroll
    for (int i = 0; i < 4; i++)
#pragma unroll
        for (int j = 0; j < 8; j++) acc[i][j] = 0.f;

    const int kbeg = kc * 256, kend = kbeg + 256;
    for (int k0 = kbeg; k0 < kend; k0 += 16) {
        float4 xv = *(const float4*)(X + (size_t)lm * 1024 + k0 + lk);
        float4 w0 = *(const float4*)(W + (size_t)(k0 + lk2) * 1024 + n0 + ln);
        float4 w1 = *(const float4*)(W + (size_t)(k0 + lk2) * 1024 + n0 + ln + 4);
        __syncthreads();
        Xs[(lk + 0) * 64 + lm] = xv.x;
        Xs[(lk + 1) * 64 + lm] = xv.y;
        Xs[(lk + 2) * 64 + lm] = xv.z;
        Xs[(lk + 3) * 64 + lm] = xv.w;
        *(float4*)(Ws + lk2 * 128 + ln) = w0;
        *(float4*)(Ws + lk2 * 128 + ln + 4) = w1;
        __syncthreads();
#pragma unroll
        for (int kk = 0; kk < 16; kk++) {
            float4 a = *(const float4*)(Xs + kk * 64 + (ty << 2));
            float4 b0 = *(const float4*)(Ws + kk * 128 + (tx << 3));
            float4 b1 = *(const float4*)(Ws + kk * 128 + (tx << 3) + 4);
            float av[4] = {a.x, a.y, a.z, a.w};
            float bv[8] = {b0.x, b0.y, b0.z, b0.w, b1.x, b1.y, b1.z, b1.w};
#pragma unroll
            for (int i = 0; i < 4; i++)
#pragma unroll
                for (int j = 0; j < 8; j++) acc[i][j] += av[i] * bv[j];
        }
    }
    float* dst = g_qv1pre + z * 65536;
#pragma unroll
    for (int i = 0; i < 4; i++)
#pragma unroll
        for (int j = 0; j < 8; j++)
            atomicAdd(&dst[((ty << 2) + i) * 1024 + n0 + (tx << 3) + j], acc[i][j]);
}

__global__ void small_finalize(const float* __restrict__ bq, const float* __restrict__ gq,
                               const float* __restrict__ gbq,
                               const float* __restrict__ bv1, const float* __restrict__ gv1,
                               const float* __restrict__ gbv1) {
    const int row = blockIdx.x;
    const int z = row >> 6, r = row & 63;
    const int tid = threadIdx.x;
    const float* pre = g_qv1pre + z * 65536 + r * 1024;
    const float* bias = z ? bv1 : bq;
    const float* gam  = z ? gv1 : gq;
    const float* bet  = z ? gbv1 : gbq;
    float v[4], s = 0.f, s2 = 0.f;
#pragma unroll
    for (int j = 0; j < 4; j++) {
        int c = tid * 4 + j;
        float x = celu_f(pre[c] + bias[c]);
        v[j] = x; s += x; s2 += x * x;
    }
#pragma unroll
    for (int o = 16; o; o >>= 1) {
        s  += __shfl_xor_sync(0xffffffffu, s, o);
        s2 += __shfl_xor_sync(0xffffffffu, s2, o);
    }
    float mu = s * (1.f / 128.f);
    float var = s2 * (1.f / 128.f) - mu * mu;
    float rs = rsqrtf(var + EPS_F);
    float* o = z ? g_v1gn : g_qgn;
#pragma unroll
    for (int j = 0; j < 4; j++) {
        int c = tid * 4 + j;
        o[r * 1024 + c] = (v[j] - mu) * rs * gam[c] + bet[c];
    }
}

// ---------------------------------------------------------------------------
// mma.sync GEMM on pre-split bf16, cp.async 3-stage pipeline, 512 threads.
// D[128x128] = X[128 x 1024] @ W[1024 x 128] via hihi+hilo+lohi.
// 16 warps (4 per SMSP) arranged 4m x 4n, warp tile 32x32 -> 32 accum regs.
// grid 4096 (512 m x 8 n).
// smem: 3 stages x 40960B (Ahi | Alo | Bhi | Blo, each 128 rows pitch 80B);
//       C epilogue aliases stage bufs; qS at end.
// ---------------------------------------------------------------------------
#define STG_B 40960
#define SMQ_OFF (3 * STG_B)
#define SM_GEMM_TOTAL (SMQ_OFF + 512)

template <bool QMUL>
__global__ void __launch_bounds__(512, 1)
gemm_kernel(const float* __restrict__ bias, const float* __restrict__ gam,
            const float* __restrict__ bet) {
    extern __shared__ char smem[];
    const uint32_t su = smem_to_u32(smem);
    const int tid = threadIdx.x, lane = tid & 31, wid = tid >> 5;
    const int mwarp = wid >> 2, nwarp = wid & 3;
    const int r0 = (int)(blockIdx.x >> 3) * 128;
    const int n0 = (int)(blockIdx.x & 7) * 128;
    const int b = r0 >> 10;

    float* qS = (float*)(smem + SMQ_OFF);
    if (QMUL && tid < 128) qS[tid] = g_qgn[b * 1024 + n0 + tid];

    const int rowL = (lane & 7) + ((lane >> 3) & 1) * 8;
    const int kL8 = (lane >> 4) * 8;
    const uint32_t lmoff = (uint32_t)(rowL * 80 + kL8 * 2);

    // staging: 512 threads, each copies one (row, 16B-seg) of Ahi/Alo/Bhi/Blo
    const int srow = tid >> 2, sseg = tid & 3;
    const __nv_bfloat16* Axh = g_xhi + (size_t)(r0 + srow) * 1024 + sseg * 8;
    const __nv_bfloat16* Axl = g_xlo + (size_t)(r0 + srow) * 1024 + sseg * 8;
    const __nv_bfloat16* Bwh = g_wthi + (size_t)(n0 + srow) * 1024 + sseg * 8;
    const __nv_bfloat16* Bwl = g_wtlo + (size_t)(n0 + srow) * 1024 + sseg * 8;
    const uint32_t dA = su + srow * 80 + sseg * 16;

#define STAGE(s, c) do { \
    if ((c) < 32) { \
        const int _k0 = (c) << 5; \
        const uint32_t _d = dA + (s) * STG_B; \
        cp16(_d,         Axh + _k0); \
        cp16(_d + 10240, Axl + _k0); \
        cp16(_d + 20480, Bwh + _k0); \
        cp16(_d + 30720, Bwl + _k0); \
    } \
    asm volatile("cp.async.commit_group;" ::: "memory"); \
} while (0)

    float d[2][4][4];
#pragma unroll
    for (int i = 0; i < 2; i++)
#pragma unroll
        for (int j = 0; j < 4; j++)
#pragma unroll
            for (int u = 0; u < 4; u++) d[i][j][u] = 0.f;

    STAGE(0, 0);
    STAGE(1, 1);

    for (int t = 0; t < 32; t++) {
        asm volatile("cp.async.wait_group 1;" ::: "memory");
        __syncthreads();
        STAGE((t + 2) % 3, t + 2);

        const uint32_t abase = su + (t % 3) * STG_B +
                               (uint32_t)(mwarp * 32 * 80) + lmoff;
        const uint32_t bbase = su + (t % 3) * STG_B + 20480 +
                               (uint32_t)(nwarp * 32 * 80) + lmoff;
#pragma unroll
        for (int sl = 0; sl < 2; sl++) {
            uint32_t Ah[2][4], Al[2][4], Bh[4][2], Bl[4][2];
#pragma unroll
            for (int fm = 0; fm < 2; fm++) {
                ldsm4(Ah[fm], abase + fm * (16 * 80) + sl * 32);
                ldsm4(Al[fm], abase + 10240 + fm * (16 * 80) + sl * 32);
            }
#pragma unroll
            for (int g = 0; g < 2; g++) {
                uint32_t tm[4];
                ldsm4(tm, bbase + g * (16 * 80) + sl * 32);
                Bh[2 * g][0] = tm[0]; Bh[2 * g][1] = tm[2];
                Bh[2 * g + 1][0] = tm[1]; Bh[2 * g + 1][1] = tm[3];
                ldsm4(tm, bbase + 10240 + g * (16 * 80) + sl * 32);
                Bl[2 * g][0] = tm[0]; Bl[2 * g][1] = tm[2];
                Bl[2 * g + 1][0] = tm[1]; Bl[2 * g + 1][1] = tm[3];
            }
#pragma unroll
            for (int fm = 0; fm < 2; fm++)
#pragma unroll
                for (int fn = 0; fn < 4; fn++) {
                    mma16816(d[fm][fn], Ah[fm], Bh[fn][0], Bh[fn][1]);
                    mma16816(d[fm][fn], Ah[fm], Bl[fn][0], Bl[fn][1]);
                    mma16816(d[fm][fn], Al[fm], Bh[fn][0], Bh[fn][1]);
                }
        }
        __syncthreads();
    }

    // ---- epilogue: frags -> smem (aliases stage bufs), per-row celu+GN ----
    float* Cs = (float*)smem;
    {
        const int mb = mwarp * 32, nb = nwarp * 32;
        const int r = lane >> 2, c = (lane & 3) * 2;
#pragma unroll
        for (int fm = 0; fm < 2; fm++)
#pragma unroll
            for (int fn = 0; fn < 4; fn++) {
                const int rr = mb + fm * 16 + r;
                const int cc = nb + fn * 8 + c;
                *(float2*)&Cs[rr * 132 + cc] = make_float2(d[fm][fn][0], d[fm][fn][1]);
                *(float2*)&Cs[(rr + 8) * 132 + cc] = make_float2(d[fm][fn][2], d[fm][fn][3]);
            }
    }
    __syncthreads();
    {
        const int row = tid >> 2, q = tid & 3;
        const int c0 = q * 32;
        float v[32];
        float s = 0.f, s2 = 0.f;
#pragma unroll
        for (int j = 0; j < 8; j++) {
            float4 x4 = *(const float4*)&Cs[row * 132 + c0 + j * 4];
            float* px = (float*)&x4;
#pragma unroll
            for (int u = 0; u < 4; u++) {
                float x = celu_f(px[u] + __ldg(&bias[n0 + c0 + j * 4 + u]));
                v[j * 4 + u] = x; s += x; s2 += x * x;
            }
        }
        s  += __shfl_xor_sync(0xffffffffu, s, 1);
        s2 += __shfl_xor_sync(0xffffffffu, s2, 1);
        s  += __shfl_xor_sync(0xffffffffu, s, 2);
        s2 += __shfl_xor_sync(0xffffffffu, s2, 2);
        const float mu = s * (1.f / 128.f);
        const float rs = rsqrtf(s2 * (1.f / 128.f) - mu * mu + EPS_F);
        float* outp = (QMUL ? g_kq : g_v2) + (size_t)(r0 + row) * 1024 + n0 + c0;
#pragma unroll
        for (int j = 0; j < 8; j++) {
            float4 o;
            float* po = (float*)&o;
#pragma unroll
            for (int u = 0; u < 4; u++) {
                const int ch = n0 + c0 + j * 4 + u;
                float xn = (v[j * 4 + u] - mu) * rs * __ldg(&gam[ch]) + __ldg(&bet[ch]);
                if (QMUL) xn *= qS[c0 + j * 4 + u];
                po[u] = xn;
            }
            *(float4*)(outp + j * 4) = o;
        }
    }
#undef STAGE
}

// ---------------------------------------------------------------------------
// attn: am = relu(g_kq @ Wb + bb); logits = am@Wl+bl; ampool partials.
// ---------------------------------------------------------------------------
__global__ void __launch_bounds__(256, 2)
attn_kernel(const float* __restrict__ Wb, const float* __restrict__ bb,
            const float* __restrict__ Wl, const float* __restrict__ bl,
            const float* __restrict__ mask) {
    __shared__ float WbS[8192];
    __shared__ float WlS[64], bbS[64], mS[64], apS[64];
    const int tid = threadIdx.x;
    const int ty = tid >> 4, tx = tid & 15;
    const int r0 = blockIdx.x << 6;
    const int b = r0 >> 10, mbase = r0 & 1023;

    for (int i = tid; i < 8192; i += 256) WbS[i] = Wb[i];
    if (tid < 64) {
        WlS[tid] = Wl[tid];
        bbS[tid] = bb[tid];
        mS[tid] = mask[r0 + tid];
    }
    __syncthreads();

    for (int g = 0; g < 8; ++g) {
        if (tid < 64) apS[tid] = 0.f;
        __syncthreads();

        float am[4][4];
#pragma unroll
        for (int i = 0; i < 4; i++)
#pragma unroll
            for (int j = 0; j < 4; j++) am[i][j] = 0.f;

        const float* sp = g_kq + (size_t)r0 * 1024 + (g << 7);
        for (int k4 = 0; k4 < 128; k4 += 4) {
            float4 av[4];
#pragma unroll
            for (int i = 0; i < 4; i++)
                av[i] = *(const float4*)(sp + (size_t)((ty << 2) + i) * 1024 + k4);
            float4 b0 = *(const float4*)(WbS + (k4 + 0) * 64 + (tx << 2));
            float4 b1 = *(const float4*)(WbS + (k4 + 1) * 64 + (tx << 2));
            float4 b2 = *(const float4*)(WbS + (k4 + 2) * 64 + (tx << 2));
            float4 b3 = *(const float4*)(WbS + (k4 + 3) * 64 + (tx << 2));
#pragma unroll
            for (int i = 0; i < 4; i++) {
                am[i][0] += av[i].x * b0.x; am[i][1] += av[i].x * b0.y;
                am[i][2] += av[i].x * b0.z; am[i][3] += av[i].x * b0.w;
                am[i][0] += av[i].y * b1.x; am[i][1] += av[i].y * b1.y;
                am[i][2] += av[i].y * b1.z; am[i][3] += av[i].y * b1.w;
                am[i][0] += av[i].z * b2.x; am[i][1] += av[i].z * b2.y;
                am[i][2] += av[i].z * b2.z; am[i][3] += av[i].z * b2.w;
                am[i][0] += av[i].w * b3.x; am[i][1] += av[i].w * b3.y;
                am[i][2] += av[i].w * b3.z; am[i][3] += av[i].w * b3.w;
            }
        }

        float lp[4];
#pragma unroll
        for (int i = 0; i < 4; i++) {
            float t = 0.f;
#pragma unroll
            for (int j = 0; j < 4; j++) {
                float a = fmaxf(am[i][j] + bbS[(tx << 2) + j], 0.f);
                am[i][j] = a;
                t += a * WlS[(tx << 2) + j];
            }
            lp[i] = t;
        }
#pragma unroll
        for (int o = 8; o; o >>= 1)
#pragma unroll
            for (int i = 0; i < 4; i++) lp[i] += __shfl_xor_sync(0xffffffffu, lp[i], o);
        if (tx == 0) {
            const float blv = __ldg(&bl[0]);
#pragma unroll
            for (int i = 0; i < 4; i++)
                g_logits[(((b << 3) + g) << 10) + mbase + (ty << 2) + i] = lp[i] + blv;
        }
#pragma unroll
        for (int j = 0; j < 4; j++) {
            float ap = am[0][j] * mS[(ty << 2) + 0] + am[1][j] * mS[(ty << 2) + 1] +
                       am[2][j] * mS[(ty << 2) + 2] + am[3][j] * mS[(ty << 2) + 3];
            atomicAdd(&apS[(tx << 2) + j], ap);
        }
        __syncthreads();
        if (tid < 64)
            atomicAdd(&g_ampool[(((b << 3) + g) << 6) + tid], apS[tid]);
        __syncthreads();
    }
}

// ---------------- finalize ----------------
__global__ void final_kernel(const float* __restrict__ mask,
                             const float* __restrict__ Wl2,
                             const float* __restrict__ bl2,
                             float* __restrict__ out) {
    const int h = blockIdx.x, b = blockIdx.y;
    const int tid = threadIdx.x;
    const int lane = tid & 31, wrp = tid >> 5;
    __shared__ float wsm[1024];
    __shared__ float redA[8], redB[8], bc[4];
    __shared__ float pm[64], ac[128], psm[256];

    const float* lg = g_logits + (((size_t)b * 8 + h) << 10);
    const float* mrow = mask + ((size_t)b << 10);

    float l[4], mk[4];
    float lmax = -1e30f, msum = 0.f;
#pragma unroll
    for (int k = 0; k < 4; k++) {
        int m = tid + (k << 8);
        mk[k] = mrow[m];
        l[k] = (mk[k] == 0.f) ? -1e9f : lg[m];
        lmax = fmaxf(lmax, l[k]);
        msum += mk[k];
    }
#pragma unroll
    for (int o = 16; o; o >>= 1) {
        lmax = fmaxf(lmax, __shfl_xor_sync(0xffffffffu, lmax, o));
        msum += __shfl_xor_sync(0xffffffffu, msum, o);
    }
    if (lane == 0) { redA[wrp] = lmax; redB[wrp] = msum; }
    __syncthreads();
    if (tid == 0) {
        float a = -1e30f, s = 0.f;
#pragma unroll
        for (int i = 0; i < 8; i++) { a = fmaxf(a, redA[i]); s += redB[i]; }
        bc[0] = a; bc[1] = s;
    }
    __syncthreads();
    const float gmax = bc[0], msumv = bc[1];

    float es = 0.f;
#pragma unroll
    for (int k = 0; k < 4; k++) {
        float e = __expf(l[k] - gmax);
        wsm[tid + (k << 8)] = e;
        es += e;
    }
#pragma unroll
    for (int o = 16; o; o >>= 1) es += __shfl_xor_sync(0xffffffffu, es, o);
    if (lane == 0) redA[wrp] = es;
    __syncthreads();
    if (tid == 0) {
        float s = 0.f;
#pragma unroll
        for (int i = 0; i < 8; i++) s += redA[i];
        bc[2] = s;
    }
    if (tid < 64) pm[tid] = g_ampool[(((b << 3) + h) << 6) + tid] / msumv;
    __syncthreads();
    const float inv = 1.f / bc[2];

    if (tid < 128) {
        float t = bl2[tid];
#pragma unroll 8
        for (int n = 0; n < 64; n++) t += pm[n] * Wl2[n * 128 + tid];
        ac[tid] = 1.f / (1.f + __expf(-t));
    }
    __syncthreads();

    const int s2 = tid >> 7, d = tid & 127;
    const float* v2p = g_v2 + ((size_t)(b << 10)) * 1024 + (h << 7) + d;
    float accp = 0.f;
    for (int m = s2; m < 1024; m += 8) {
        accp += wsm[m] * v2p[(size_t)m * 1024];
        accp += wsm[m + 2] * v2p[(size_t)(m + 2) * 1024];
        accp += wsm[m + 4] * v2p[(size_t)(m + 4) * 1024];
        accp += wsm[m + 6] * v2p[(size_t)(m + 6) * 1024];
    }
    psm[tid] = accp;
    __syncthreads();
    if (tid < 128) {
        float p = (psm[tid] + psm[tid + 128]) * inv;
        int oi = (b << 10) + (h << 7) + tid;
        out[oi] = g_v1gn[oi] * p * ac[tid];
    }
}

// ---------------- launch ----------------
extern "C" void kernel_launch(void* const* d_in, const int* in_sizes, int n_in,
                              void* d_out, int out_size) {
    const float* query  = (const float*)d_in[0];
    const float* key    = (const float*)d_in[1];
    const float* mask   = (const float*)d_in[2];
    const float* value1 = (const float*)d_in[3];
    const float* value2 = (const float*)d_in[4];
    const float* Wq  = (const float*)d_in[5];
    const float* bq  = (const float*)d_in[6];
    const float* gq  = (const float*)d_in[7];
    const float* gbq = (const float*)d_in[8];
    const float* Wk  = (const float*)d_in[9];
    const float* bk  = (const float*)d_in[10];
    const float* gk  = (const float*)d_in[11];
    const float* gbk = (const float*)d_in[12];
    const float* Wv1  = (const float*)d_in[13];
    const float* bv1  = (const float*)d_in[14];
    const float* gv1  = (const float*)d_in[15];
    const float* gbv1 = (const float*)d_in[16];
    const float* Wv2  = (const float*)d_in[17];
    const float* bv2  = (const float*)d_in[18];
    const float* gv2  = (const float*)d_in[19];
    const float* gbv2 = (const float*)d_in[20];
    const float* Wb  = (const float*)d_in[21];
    const float* bb  = (const float*)d_in[22];
    const float* Wl  = (const float*)d_in[23];
    const float* bl  = (const float*)d_in[24];
    const float* Wl2 = (const float*)d_in[25];
    const float* bl2 = (const float*)d_in[26];
    float* out = (float*)d_out;

    cudaFuncSetAttribute(gemm_kernel<true>,  cudaFuncAttributeMaxDynamicSharedMemorySize,
                         SM_GEMM_TOTAL);
    cudaFuncSetAttribute(gemm_kernel<false>, cudaFuncAttributeMaxDynamicSharedMemorySize,
                         SM_GEMM_TOTAL);

    zero_kernel<<<512, 256>>>();
    small_partial<<<dim3(8, 4, 2), 256>>>(query, value1, Wq, Wv1);
    small_finalize<<<128, 256>>>(bq, gq, gbq, bv1, gv1, gbv1);

    // k branch
    split_x<<<65536, 256>>>(key);
    split_w<<<dim3(32, 32), 256>>>(Wk);
    gemm_kernel<true><<<4096, 512, SM_GEMM_TOTAL>>>(bk, gk, gbk);

    // v2 branch (reuses split buffers)
    split_x<<<65536, 256>>>(value2);
    split_w<<<dim3(32, 32), 256>>>(Wv2);
    gemm_kernel<false><<<4096, 512, SM_GEMM_TOTAL>>>(bv2, gv2, gbv2);

    attn_kernel<<<1024, 256>>>(Wb, bb, Wl, bl, mask);
    final_kernel<<<dim3(8, 64), 256>>>(mask, Wl2, bl2, out);
}

// round 14
// speedup vs baseline: 1.1410x; 1.0614x over previous
#include <cuda_runtime.h>
#include <cuda_bf16.h>
#include <cstdint>

#define EPS_F 1e-5f

__device__ float g_v2[67108864];      // (B*M, 1024) v2 after celu+GN
__device__ __nv_bfloat16 g_xhi[67108864];   // X split hi (row-major)
__device__ __nv_bfloat16 g_xlo[67108864];   // X split lo
__device__ __nv_bfloat16 g_wthi[1048576];   // W^T split hi  [n][k]
__device__ __nv_bfloat16 g_wtlo[1048576];   // W^T split lo  [n][k]
__device__ float g_qgn[65536];
__device__ float g_v1gn[65536];
__device__ float g_qv1pre[131072];
__device__ float g_logits[524288];    // (B, H, M)
__device__ float g_ampool[32768];     // (B, H, 64)

// ---------------- helpers ----------------
__device__ __forceinline__ uint32_t smem_to_u32(const void* p) {
    uint32_t a;
    asm("{ .reg .u64 t; cvta.to.shared.u64 t, %1; cvt.u32.u64 %0, t; }" : "=r"(a) : "l"(p));
    return a;
}
__device__ __forceinline__ float celu_f(float x) {
    return x > 0.f ? x : 1.3f * expm1f(x * (1.0f / 1.3f));
}
__device__ __forceinline__ void cvt_split2(float a, float b, uint32_t& hi, uint32_t& lo) {
    __nv_bfloat16 ha = __float2bfloat16(a);
    __nv_bfloat16 hb = __float2bfloat16(b);
    __nv_bfloat16 la = __float2bfloat16(a - __bfloat162float(ha));
    __nv_bfloat16 lb = __float2bfloat16(b - __bfloat162float(hb));
    __nv_bfloat162 h2(ha, hb), l2(la, lb);
    hi = *reinterpret_cast<uint32_t*>(&h2);
    lo = *reinterpret_cast<uint32_t*>(&l2);
}
__device__ __forceinline__ void ldsm4(uint32_t* r, uint32_t addr) {
    asm volatile("ldmatrix.sync.aligned.m8n8.x4.shared.b16 {%0,%1,%2,%3}, [%4];"
                 : "=r"(r[0]), "=r"(r[1]), "=r"(r[2]), "=r"(r[3]) : "r"(addr));
}
__device__ __forceinline__ void mma16816(float* d, const uint32_t* a,
                                         const uint32_t b0, const uint32_t b1) {
    asm volatile(
        "mma.sync.aligned.m16n8k16.row.col.f32.bf16.bf16.f32 "
        "{%0,%1,%2,%3}, {%4,%5,%6,%7}, {%8,%9}, {%0,%1,%2,%3};"
        : "+f"(d[0]), "+f"(d[1]), "+f"(d[2]), "+f"(d[3])
        : "r"(a[0]), "r"(a[1]), "r"(a[2]), "r"(a[3]), "r"(b0), "r"(b1));
}
__device__ __forceinline__ void cp16(uint32_t dst, const void* src) {
    asm volatile("cp.async.cg.shared.global [%0], [%1], 16;" :: "r"(dst), "l"(src) : "memory");
}

// ---------------- zero scratch ----------------
__global__ void zero_kernel() {
    int i = blockIdx.x * 256 + threadIdx.x;
    if (i < 32768)  g_ampool[i] = 0.f;
    if (i < 131072) g_qv1pre[i] = 0.f;
}

// ---------------- split passes ----------------
__global__ void split_x(const float* __restrict__ X) {
    size_t i = ((size_t)blockIdx.x * 256 + threadIdx.x) * 4;
    float4 v = *(const float4*)(X + i);
    uint32_t h0, l0, h1, l1;
    cvt_split2(v.x, v.y, h0, l0);
    cvt_split2(v.z, v.w, h1, l1);
    *(uint2*)(g_xhi + i) = make_uint2(h0, h1);
    *(uint2*)(g_xlo + i) = make_uint2(l0, l1);
}

// transpose + split: W[k][n] -> g_wthi/lo[n][k]
__global__ void split_w(const float* __restrict__ W) {
    __shared__ float tile[32][33];
    const int kt = blockIdx.x * 32, nt = blockIdx.y * 32;
    const int tx = threadIdx.x & 31, ty = threadIdx.x >> 5;   // 256 thr
#pragma unroll
    for (int j = 0; j < 4; j++)
        tile[ty + j * 8][tx] = W[(size_t)(kt + ty + j * 8) * 1024 + nt + tx];
    __syncthreads();
#pragma unroll
    for (int j = 0; j < 4; j++) {
        const int n = nt + ty + j * 8, k = kt + tx;
        float v = tile[tx][ty + j * 8];
        __nv_bfloat16 h = __float2bfloat16(v);
        __nv_bfloat16 l = __float2bfloat16(v - __bfloat162float(h));
        g_wthi[(size_t)n * 1024 + k] = h;
        g_wtlo[(size_t)n * 1024 + k] = l;
    }
}

// ---------------- small branches (q, v1) ----------------
__global__ void small_partial(const float* __restrict__ query,
                              const float* __restrict__ value1,
                              const float* __restrict__ Wq,
                              const float* __restrict__ Wv1) {
    const int g = blockIdx.x, kc = blockIdx.y, z = blockIdx.z;
    const float* X = z ? value1 : query;
    const float* W = z ? Wv1 : Wq;
    __shared__ float Xs[16 * 64];
    __shared__ float Ws[16 * 128];
    const int tid = threadIdx.x;
    const int ty = tid >> 4, tx = tid & 15;
    const int n0 = g << 7;
    const int lm = tid >> 2, lk = (tid & 3) << 2;
    const int lk2 = tid >> 4, ln = (tid & 15) << 3;

    float acc[4][8];
#pragma unroll
    for (int i = 0; i < 4; i++)
#pragma unroll
        for (int j = 0; j < 8; j++) acc[i][j] = 0.f;

    const int kbeg = kc * 256, kend = kbeg + 256;
    for (int k0 = kbeg; k0 < kend; k0 += 16) {
        float4 xv = *(const float4*)(X + (size_t)lm * 1024 + k0 + lk);
        float4 w0 = *(const float4*)(W + (size_t)(k0 + lk2) * 1024 + n0 + ln);
        float4 w1 = *(const float4*)(W + (size_t)(k0 + lk2) * 1024 + n0 + ln + 4);
        __syncthreads();
        Xs[(lk + 0) * 64 + lm] = xv.x;
        Xs[(lk + 1) * 64 + lm] = xv.y;
        Xs[(lk + 2) * 64 + lm] = xv.z;
        Xs[(lk + 3) * 64 + lm] = xv.w;
        *(float4*)(Ws + lk2 * 128 + ln) = w0;
        *(float4*)(Ws + lk2 * 128 + ln + 4) = w1;
        __syncthreads();
#pragma unroll
        for (int kk = 0; kk < 16; kk++) {
            float4 a = *(const float4*)(Xs + kk * 64 + (ty << 2));
            float4 b0 = *(const float4*)(Ws + kk * 128 + (tx << 3));
            float4 b1 = *(const float4*)(Ws + kk * 128 + (tx << 3) + 4);
            float av[4] = {a.x, a.y, a.z, a.w};
            float bv[8] = {b0.x, b0.y, b0.z, b0.w, b1.x, b1.y, b1.z, b1.w};
#pragma unroll
            for (int i = 0; i < 4; i++)
#pragma unroll
                for (int j = 0; j < 8; j++) acc[i][j] += av[i] * bv[j];
        }
    }
    float* dst = g_qv1pre + z * 65536;
#pragma unroll
    for (int i = 0; i < 4; i++)
#pragma unroll
        for (int j = 0; j < 8; j++)
            atomicAdd(&dst[((ty << 2) + i) * 1024 + n0 + (tx << 3) + j], acc[i][j]);
}

__global__ void small_finalize(const float* __restrict__ bq, const float* __restrict__ gq,
                               const float* __restrict__ gbq,
                               const float* __restrict__ bv1, const float* __restrict__ gv1,
                               const float* __restrict__ gbv1) {
    const int row = blockIdx.x;
    const int z = row >> 6, r = row & 63;
    const int tid = threadIdx.x;
    const float* pre = g_qv1pre + z * 65536 + r * 1024;
    const float* bias = z ? bv1 : bq;
    const float* gam  = z ? gv1 : gq;
    const float* bet  = z ? gbv1 : gbq;
    float v[4], s = 0.f, s2 = 0.f;
#pragma unroll
    for (int j = 0; j < 4; j++) {
        int c = tid * 4 + j;
        float x = celu_f(pre[c] + bias[c]);
        v[j] = x; s += x; s2 += x * x;
    }
#pragma unroll
    for (int o = 16; o; o >>= 1) {
        s  += __shfl_xor_sync(0xffffffffu, s, o);
        s2 += __shfl_xor_sync(0xffffffffu, s2, o);
    }
    float mu = s * (1.f / 128.f);
    float var = s2 * (1.f / 128.f) - mu * mu;
    float rs = rsqrtf(var + EPS_F);
    float* o = z ? g_v1gn : g_qgn;
#pragma unroll
    for (int j = 0; j < 4; j++) {
        int c = tid * 4 + j;
        o[r * 1024 + c] = (v[j] - mu) * rs * gam[c] + bet[c];
    }
}

// ---------------------------------------------------------------------------
// mma.sync GEMM on pre-split bf16, cp.async 3-stage pipeline, 512 threads.
// D[128x128] = X[128 x 1024] @ W[1024 x 128] via hihi+hilo+lohi.
// 16 warps (4/SMSP) 4m x 4n, warp tile 32x32. grid 4096 (512 m x 8 n).
// Mainloop: ONE barrier per k-iter; all 16 ldsm hoisted ahead of 48 mma.
// Epilogue: celu+GN; QMUL additionally fuses the attention stage
// (kq=GN*q back into Cs, am=relu(kq@Wb+bb), logits=am@Wl+bl, am_pool).
// smem: [3 x 40960 stages | qS 512 | WbS 32768 | WlS 256 | bbS 256 | mS 512 | apS 256]
// ---------------------------------------------------------------------------
#define STG_B 40960
#define SMQ_OFF  (3 * STG_B)              // 122880
#define SMWB_OFF (SMQ_OFF + 512)          // 123392
#define SMWL_OFF (SMWB_OFF + 32768)       // 156160
#define SMBB_OFF (SMWL_OFF + 256)         // 156416
#define SMMS_OFF (SMBB_OFF + 256)         // 156672
#define SMAP_OFF (SMMS_OFF + 512)         // 157184
#define SM_GEMM_TOTAL (SMAP_OFF + 256)    // 157440

template <bool QMUL>
__global__ void __launch_bounds__(512, 1)
gemm_kernel(const float* __restrict__ bias, const float* __restrict__ gam,
            const float* __restrict__ bet,
            const float* __restrict__ Wb, const float* __restrict__ bb,
            const float* __restrict__ Wl, const float* __restrict__ bl,
            const float* __restrict__ mask) {
    extern __shared__ char smem[];
    const uint32_t su = smem_to_u32(smem);
    const int tid = threadIdx.x, lane = tid & 31, wid = tid >> 5;
    const int mwarp = wid >> 2, nwarp = wid & 3;
    const int r0 = (int)(blockIdx.x >> 3) * 128;
    const int n0 = (int)(blockIdx.x & 7) * 128;
    const int b = r0 >> 10;
    const int g = (int)(blockIdx.x & 7);
    const int mbase = r0 & 1023;

    float* qS  = (float*)(smem + SMQ_OFF);
    float* WbS = (float*)(smem + SMWB_OFF);
    float* WlS = (float*)(smem + SMWL_OFF);
    float* bbS = (float*)(smem + SMBB_OFF);
    float* mS  = (float*)(smem + SMMS_OFF);
    float* apS = (float*)(smem + SMAP_OFF);

    if (QMUL) {
        for (int i = tid; i < 8192; i += 512) WbS[i] = Wb[i];
        if (tid < 128) {
            qS[tid] = g_qgn[b * 1024 + n0 + tid];
            mS[tid] = mask[r0 + tid];
        }
        if (tid < 64) {
            WlS[tid] = Wl[tid];
            bbS[tid] = bb[tid];
            apS[tid] = 0.f;
        }
    }

    const int rowL = (lane & 7) + ((lane >> 3) & 1) * 8;
    const int kL8 = (lane >> 4) * 8;
    const uint32_t lmoff = (uint32_t)(rowL * 80 + kL8 * 2);

    // staging: 512 threads, each copies one (row, 16B-seg) of Ahi/Alo/Bhi/Blo
    const int srow = tid >> 2, sseg = tid & 3;
    const __nv_bfloat16* Axh = g_xhi + (size_t)(r0 + srow) * 1024 + sseg * 8;
    const __nv_bfloat16* Axl = g_xlo + (size_t)(r0 + srow) * 1024 + sseg * 8;
    const __nv_bfloat16* Bwh = g_wthi + (size_t)(n0 + srow) * 1024 + sseg * 8;
    const __nv_bfloat16* Bwl = g_wtlo + (size_t)(n0 + srow) * 1024 + sseg * 8;
    const uint32_t dA = su + srow * 80 + sseg * 16;

#define STAGE(s, c) do { \
    if ((c) < 32) { \
        const int _k0 = (c) << 5; \
        const uint32_t _d = dA + (s) * STG_B; \
        cp16(_d,         Axh + _k0); \
        cp16(_d + 10240, Axl + _k0); \
        cp16(_d + 20480, Bwh + _k0); \
        cp16(_d + 30720, Bwl + _k0); \
    } \
    asm volatile("cp.async.commit_group;" ::: "memory"); \
} while (0)

    float d[2][4][4];
#pragma unroll
    for (int i = 0; i < 2; i++)
#pragma unroll
        for (int j = 0; j < 4; j++)
#pragma unroll
            for (int u = 0; u < 4; u++) d[i][j][u] = 0.f;

    STAGE(0, 0);
    STAGE(1, 1);

    for (int t = 0; t < 32; t++) {
        asm volatile("cp.async.wait_group 1;" ::: "memory");
        __syncthreads();            // data of buf t%3 visible; prev iter reads done
        STAGE((t + 2) % 3, t + 2);  // safe: buf (t+2)%3 last read at iter t-1

        const uint32_t abase = su + (t % 3) * STG_B +
                               (uint32_t)(mwarp * 32 * 80) + lmoff;
        const uint32_t bbase = su + (t % 3) * STG_B + 20480 +
                               (uint32_t)(nwarp * 32 * 80) + lmoff;
        // hoist ALL fragment loads (16 ldsm) ahead of ALL 48 mma
        uint32_t Ah[2][2][4], Al[2][2][4], Bh[2][4][2], Bl[2][4][2];
#pragma unroll
        for (int sl = 0; sl < 2; sl++) {
#pragma unroll
            for (int fm = 0; fm < 2; fm++) {
                ldsm4(Ah[sl][fm], abase + fm * (16 * 80) + sl * 32);
                ldsm4(Al[sl][fm], abase + 10240 + fm * (16 * 80) + sl * 32);
            }
#pragma unroll
            for (int gg = 0; gg < 2; gg++) {
                uint32_t tm[4];
                ldsm4(tm, bbase + gg * (16 * 80) + sl * 32);
                Bh[sl][2 * gg][0] = tm[0]; Bh[sl][2 * gg][1] = tm[2];
                Bh[sl][2 * gg + 1][0] = tm[1]; Bh[sl][2 * gg + 1][1] = tm[3];
                ldsm4(tm, bbase + 10240 + gg * (16 * 80) + sl * 32);
                Bl[sl][2 * gg][0] = tm[0]; Bl[sl][2 * gg][1] = tm[2];
                Bl[sl][2 * gg + 1][0] = tm[1]; Bl[sl][2 * gg + 1][1] = tm[3];
            }
        }
#pragma unroll
        for (int sl = 0; sl < 2; sl++)
#pragma unroll
            for (int fm = 0; fm < 2; fm++)
#pragma unroll
                for (int fn = 0; fn < 4; fn++) {
                    mma16816(d[fm][fn], Ah[sl][fm], Bh[sl][fn][0], Bh[sl][fn][1]);
                    mma16816(d[fm][fn], Ah[sl][fm], Bl[sl][fn][0], Bl[sl][fn][1]);
                    mma16816(d[fm][fn], Al[sl][fm], Bh[sl][fn][0], Bh[sl][fn][1]);
                }
    }
    asm volatile("cp.async.wait_group 0;" ::: "memory");
    __syncthreads();   // all compute done before aliasing stage bufs as Cs

    // ---- epilogue: frags -> Cs (aliases stage bufs) ----
    float* Cs = (float*)smem;
    {
        const int mb = mwarp * 32, nb = nwarp * 32;
        const int r = lane >> 2, c = (lane & 3) * 2;
#pragma unroll
        for (int fm = 0; fm < 2; fm++)
#pragma unroll
            for (int fn = 0; fn < 4; fn++) {
                const int rr = mb + fm * 16 + r;
                const int cc = nb + fn * 8 + c;
                *(float2*)&Cs[rr * 132 + cc] = make_float2(d[fm][fn][0], d[fm][fn][1]);
                *(float2*)&Cs[(rr + 8) * 132 + cc] = make_float2(d[fm][fn][2], d[fm][fn][3]);
            }
    }
    __syncthreads();

    // ---- per-row bias + celu + GN; QMUL: kq back into Cs, else -> g_v2 ----
    {
        const int row = tid >> 2, q = tid & 3;
        const int c0 = q * 32;
        float v[32];
        float s = 0.f, s2 = 0.f;
#pragma unroll
        for (int j = 0; j < 8; j++) {
            float4 x4 = *(const float4*)&Cs[row * 132 + c0 + j * 4];
            float* px = (float*)&x4;
#pragma unroll
            for (int u = 0; u < 4; u++) {
                float x = celu_f(px[u] + __ldg(&bias[n0 + c0 + j * 4 + u]));
                v[j * 4 + u] = x; s += x; s2 += x * x;
            }
        }
        s  += __shfl_xor_sync(0xffffffffu, s, 1);
        s2 += __shfl_xor_sync(0xffffffffu, s2, 1);
        s  += __shfl_xor_sync(0xffffffffu, s, 2);
        s2 += __shfl_xor_sync(0xffffffffu, s2, 2);
        const float mu = s * (1.f / 128.f);
        const float rs = rsqrtf(s2 * (1.f / 128.f) - mu * mu + EPS_F);
        if (QMUL) {
#pragma unroll
            for (int j = 0; j < 8; j++) {
                float4 o;
                float* po = (float*)&o;
#pragma unroll
                for (int u = 0; u < 4; u++) {
                    const int ch = n0 + c0 + j * 4 + u;
                    float xn = (v[j * 4 + u] - mu) * rs * __ldg(&gam[ch]) + __ldg(&bet[ch]);
                    po[u] = xn * qS[c0 + j * 4 + u];
                }
                *(float4*)&Cs[row * 132 + c0 + j * 4] = o;
            }
        } else {
            float* outp = g_v2 + (size_t)(r0 + row) * 1024 + n0 + c0;
#pragma unroll
            for (int j = 0; j < 8; j++) {
                float4 o;
                float* po = (float*)&o;
#pragma unroll
                for (int u = 0; u < 4; u++) {
                    const int ch = n0 + c0 + j * 4 + u;
                    po[u] = (v[j * 4 + u] - mu) * rs * __ldg(&gam[ch]) + __ldg(&bet[ch]);
                }
                *(float4*)(outp + j * 4) = o;
            }
        }
    }

    // ---- fused attention stage (QMUL only): am, logits, am_pool ----
    if (QMUL) {
        __syncthreads();  // Cs now holds kq for the full 128x128 head tile
        const int ty = tid >> 4, tx = tid & 15;   // 32 x 16; thread tile 4x4

        float am[4][4];
#pragma unroll
        for (int i = 0; i < 4; i++)
#pragma unroll
            for (int j = 0; j < 4; j++) am[i][j] = 0.f;

        for (int k4 = 0; k4 < 128; k4 += 4) {
            float4 av[4];
#pragma unroll
            for (int i = 0; i < 4; i++)
                av[i] = *(const float4*)&Cs[((ty << 2) + i) * 132 + k4];
            float4 b0 = *(const float4*)(WbS + (k4 + 0) * 64 + (tx << 2));
            float4 b1 = *(const float4*)(WbS + (k4 + 1) * 64 + (tx << 2));
            float4 b2 = *(const float4*)(WbS + (k4 + 2) * 64 + (tx << 2));
            float4 b3 = *(const float4*)(WbS + (k4 + 3) * 64 + (tx << 2));
#pragma unroll
            for (int i = 0; i < 4; i++) {
                am[i][0] += av[i].x * b0.x; am[i][1] += av[i].x * b0.y;
                am[i][2] += av[i].x * b0.z; am[i][3] += av[i].x * b0.w;
                am[i][0] += av[i].y * b1.x; am[i][1] += av[i].y * b1.y;
                am[i][2] += av[i].y * b1.z; am[i][3] += av[i].y * b1.w;
                am[i][0] += av[i].z * b2.x; am[i][1] += av[i].z * b2.y;
                am[i][2] += av[i].z * b2.z; am[i][3] += av[i].z * b2.w;
                am[i][0] += av[i].w * b3.x; am[i][1] += av[i].w * b3.y;
                am[i][2] += av[i].w * b3.z; am[i][3] += av[i].w * b3.w;
            }
        }

        // bias + relu, logit partials (dot over this thread's 4 cols)
        float lp[4];
#pragma unroll
        for (int i = 0; i < 4; i++) {
            float t = 0.f;
#pragma unroll
            for (int j = 0; j < 4; j++) {
                float a = fmaxf(am[i][j] + bbS[(tx << 2) + j], 0.f);
                am[i][j] = a;
                t += a * WlS[(tx << 2) + j];
            }
            lp[i] = t;
        }
#pragma unroll
        for (int o = 8; o; o >>= 1)
#pragma unroll
            for (int i = 0; i < 4; i++) lp[i] += __shfl_xor_sync(0xffffffffu, lp[i], o);
        if (tx == 0) {
            const float blv = __ldg(&bl[0]);
#pragma unroll
            for (int i = 0; i < 4; i++)
                g_logits[(((b << 3) + g) << 10) + mbase + (ty << 2) + i] = lp[i] + blv;
        }
        // am_pool partials (mask-weighted row sums)
#pragma unroll
        for (int j = 0; j < 4; j++) {
            float ap = am[0][j] * mS[(ty << 2) + 0] + am[1][j] * mS[(ty << 2) + 1] +
                       am[2][j] * mS[(ty << 2) + 2] + am[3][j] * mS[(ty << 2) + 3];
            atomicAdd(&apS[(tx << 2) + j], ap);
        }
        __syncthreads();
        if (tid < 64)
            atomicAdd(&g_ampool[(((b << 3) + g) << 6) + tid], apS[tid]);
    }
#undef STAGE
}

// ---------------- finalize ----------------
__global__ void final_kernel(const float* __restrict__ mask,
                             const float* __restrict__ Wl2,
                             const float* __restrict__ bl2,
                             float* __restrict__ out) {
    const int h = blockIdx.x, b = blockIdx.y;
    const int tid = threadIdx.x;
    const int lane = tid & 31, wrp = tid >> 5;
    __shared__ float wsm[1024];
    __shared__ float redA[8], redB[8], bc[4];
    __shared__ float pm[64], ac[128], psm[256];

    const float* lg = g_logits + (((size_t)b * 8 + h) << 10);
    const float* mrow = mask + ((size_t)b << 10);

    float l[4], mk[4];
    float lmax = -1e30f, msum = 0.f;
#pragma unroll
    for (int k = 0; k < 4; k++) {
        int m = tid + (k << 8);
        mk[k] = mrow[m];
        l[k] = (mk[k] == 0.f) ? -1e9f : lg[m];
        lmax = fmaxf(lmax, l[k]);
        msum += mk[k];
    }
#pragma unroll
    for (int o = 16; o; o >>= 1) {
        lmax = fmaxf(lmax, __shfl_xor_sync(0xffffffffu, lmax, o));
        msum += __shfl_xor_sync(0xffffffffu, msum, o);
    }
    if (lane == 0) { redA[wrp] = lmax; redB[wrp] = msum; }
    __syncthreads();
    if (tid == 0) {
        float a = -1e30f, s = 0.f;
#pragma unroll
        for (int i = 0; i < 8; i++) { a = fmaxf(a, redA[i]); s += redB[i]; }
        bc[0] = a; bc[1] = s;
    }
    __syncthreads();
    const float gmax = bc[0], msumv = bc[1];

    float es = 0.f;
#pragma unroll
    for (int k = 0; k < 4; k++) {
        float e = __expf(l[k] - gmax);
        wsm[tid + (k << 8)] = e;
        es += e;
    }
#pragma unroll
    for (int o = 16; o; o >>= 1) es += __shfl_xor_sync(0xffffffffu, es, o);
    if (lane == 0) redA[wrp] = es;
    __syncthreads();
    if (tid == 0) {
        float s = 0.f;
#pragma unroll
        for (int i = 0; i < 8; i++) s += redA[i];
        bc[2] = s;
    }
    if (tid < 64) pm[tid] = g_ampool[(((b << 3) + h) << 6) + tid] / msumv;
    __syncthreads();
    const float inv = 1.f / bc[2];

    if (tid < 128) {
        float t = bl2[tid];
#pragma unroll 8
        for (int n = 0; n < 64; n++) t += pm[n] * Wl2[n * 128 + tid];
        ac[tid] = 1.f / (1.f + __expf(-t));
    }
    __syncthreads();

    const int s2 = tid >> 7, d = tid & 127;
    const float* v2p = g_v2 + ((size_t)(b << 10)) * 1024 + (h << 7) + d;
    float accp = 0.f;
    for (int m = s2; m < 1024; m += 8) {
        accp += wsm[m] * v2p[(size_t)m * 1024];
        accp += wsm[m + 2] * v2p[(size_t)(m + 2) * 1024];
        accp += wsm[m + 4] * v2p[(size_t)(m + 4) * 1024];
        accp += wsm[m + 6] * v2p[(size_t)(m + 6) * 1024];
    }
    psm[tid] = accp;
    __syncthreads();
    if (tid < 128) {
        float p = (psm[tid] + psm[tid + 128]) * inv;
        int oi = (b << 10) + (h << 7) + tid;
        out[oi] = g_v1gn[oi] * p * ac[tid];
    }
}

// ---------------- launch ----------------
extern "C" void kernel_launch(void* const* d_in, const int* in_sizes, int n_in,
                              void* d_out, int out_size) {
    const float* query  = (const float*)d_in[0];
    const float* key    = (const float*)d_in[1];
    const float* mask   = (const float*)d_in[2];
    const float* value1 = (const float*)d_in[3];
    const float* value2 = (const float*)d_in[4];
    const float* Wq  = (const float*)d_in[5];
    const float* bq  = (const float*)d_in[6];
    const float* gq  = (const float*)d_in[7];
    const float* gbq = (const float*)d_in[8];
    const float* Wk  = (const float*)d_in[9];
    const float* bk  = (const float*)d_in[10];
    const float* gk  = (const float*)d_in[11];
    const float* gbk = (const float*)d_in[12];
    const float* Wv1  = (const float*)d_in[13];
    const float* bv1  = (const float*)d_in[14];
    const float* gv1  = (const float*)d_in[15];
    const float* gbv1 = (const float*)d_in[16];
    const float* Wv2  = (const float*)d_in[17];
    const float* bv2  = (const float*)d_in[18];
    const float* gv2  = (const float*)d_in[19];
    const float* gbv2 = (const float*)d_in[20];
    const float* Wb  = (const float*)d_in[21];
    const float* bb  = (const float*)d_in[22];
    const float* Wl  = (const float*)d_in[23];
    const float* bl  = (const float*)d_in[24];
    const float* Wl2 = (const float*)d_in[25];
    const float* bl2 = (const float*)d_in[26];
    float* out = (float*)d_out;

    cudaFuncSetAttribute(gemm_kernel<true>,  cudaFuncAttributeMaxDynamicSharedMemorySize,
                         SM_GEMM_TOTAL);
    cudaFuncSetAttribute(gemm_kernel<false>, cudaFuncAttributeMaxDynamicSharedMemorySize,
                         SM_GEMM_TOTAL);

    zero_kernel<<<512, 256>>>();
    small_partial<<<dim3(8, 4, 2), 256>>>(query, value1, Wq, Wv1);
    small_finalize<<<128, 256>>>(bq, gq, gbq, bv1, gv1, gbv1);

    // k branch (fused attention epilogue)
    split_x<<<65536, 256>>>(key);
    split_w<<<dim3(32, 32), 256>>>(Wk);
    gemm_kernel<true><<<4096, 512, SM_GEMM_TOTAL>>>(bk, gk, gbk, Wb, bb, Wl, bl, mask);

    // v2 branch (reuses split buffers)
    split_x<<<65536, 256>>>(value2);
    split_w<<<dim3(32, 32), 256>>>(Wv2);
    gemm_kernel<false><<<4096, 512, SM_GEMM_TOTAL>>>(bv2, gv2, gbv2,
                                                     nullptr, nullptr, nullptr, nullptr, nullptr);

    final_kernel<<<dim3(8, 64), 256>>>(mask, Wl2, bl2, out);
}

// round 16
// speedup vs baseline: 2.1619x; 1.8947x over previous
#include <cuda_runtime.h>
#include <cuda_fp16.h>
#include <cstdint>

#define EPS_F 1e-5f

__device__ float g_v2[67108864];      // (B*M, 1024) v2 after celu+GN
__device__ __half g_xh[67108864];     // X as fp16 (row-major)
__device__ __half g_wth[1048576];     // W^T as fp16  [n][k]
__device__ float g_qgn[65536];
__device__ float g_v1gn[65536];
__device__ float g_qv1pre[131072];
__device__ float g_logits[524288];    // (B, H, M)
__device__ float g_ampool[32768];     // (B, H, 64)

// ---------------- helpers ----------------
__device__ __forceinline__ uint32_t smem_to_u32(const void* p) {
    uint32_t a;
    asm("{ .reg .u64 t; cvta.to.shared.u64 t, %1; cvt.u32.u64 %0, t; }" : "=r"(a) : "l"(p));
    return a;
}
__device__ __forceinline__ float celu_f(float x) {
    return x > 0.f ? x : 1.3f * expm1f(x * (1.0f / 1.3f));
}
__device__ __forceinline__ void ldsm4(uint32_t* r, uint32_t addr) {
    asm volatile("ldmatrix.sync.aligned.m8n8.x4.shared.b16 {%0,%1,%2,%3}, [%4];"
                 : "=r"(r[0]), "=r"(r[1]), "=r"(r[2]), "=r"(r[3]) : "r"(addr));
}
__device__ __forceinline__ void mma16816(float* d, const uint32_t* a,
                                         const uint32_t b0, const uint32_t b1) {
    asm volatile(
        "mma.sync.aligned.m16n8k16.row.col.f32.f16.f16.f32 "
        "{%0,%1,%2,%3}, {%4,%5,%6,%7}, {%8,%9}, {%0,%1,%2,%3};"
        : "+f"(d[0]), "+f"(d[1]), "+f"(d[2]), "+f"(d[3])
        : "r"(a[0]), "r"(a[1]), "r"(a[2]), "r"(a[3]), "r"(b0), "r"(b1));
}
__device__ __forceinline__ void cp16(uint32_t dst, const void* src) {
    asm volatile("cp.async.cg.shared.global [%0], [%1], 16;" :: "r"(dst), "l"(src) : "memory");
}

// ---------------- zero scratch ----------------
__global__ void zero_kernel() {
    int i = blockIdx.x * 256 + threadIdx.x;
    if (i < 32768)  g_ampool[i] = 0.f;
    if (i < 131072) g_qv1pre[i] = 0.f;
}

// ---------------- convert passes ----------------
__global__ void convert_x(const float* __restrict__ X) {
    size_t i = ((size_t)blockIdx.x * 256 + threadIdx.x) * 4;
    float4 v = *(const float4*)(X + i);
    __half2 h0(__float2half(v.x), __float2half(v.y));
    __half2 h1(__float2half(v.z), __float2half(v.w));
    *(uint2*)(g_xh + i) = make_uint2(*reinterpret_cast<uint32_t*>(&h0),
                                     *reinterpret_cast<uint32_t*>(&h1));
}

// transpose + convert: W[k][n] -> g_wth[n][k]
__global__ void convert_w(const float* __restrict__ W) {
    __shared__ float tile[32][33];
    const int kt = blockIdx.x * 32, nt = blockIdx.y * 32;
    const int tx = threadIdx.x & 31, ty = threadIdx.x >> 5;   // 256 thr
#pragma unroll
    for (int j = 0; j < 4; j++)
        tile[ty + j * 8][tx] = W[(size_t)(kt + ty + j * 8) * 1024 + nt + tx];
    __syncthreads();
#pragma unroll
    for (int j = 0; j < 4; j++) {
        const int n = nt + ty + j * 8, k = kt + tx;
        g_wth[(size_t)n * 1024 + k] = __float2half(tile[tx][ty + j * 8]);
    }
}

// ---------------- small branches (q, v1) ----------------
__global__ void small_partial(const float* __restrict__ query,
                              const float* __restrict__ value1,
                              const float* __restrict__ Wq,
                              const float* __restrict__ Wv1) {
    const int g = blockIdx.x, kc = blockIdx.y, z = blockIdx.z;
    const float* X = z ? value1 : query;
    const float* W = z ? Wv1 : Wq;
    __shared__ float Xs[16 * 64];
    __shared__ float Ws[16 * 128];
    const int tid = threadIdx.x;
    const int ty = tid >> 4, tx = tid & 15;
    const int n0 = g << 7;
    const int lm = tid >> 2, lk = (tid & 3) << 2;
    const int lk2 = tid >> 4, ln = (tid & 15) << 3;

    float acc[4][8];
#pragma unroll
    for (int i = 0; i < 4; i++)
#pragma unroll
        for (int j = 0; j < 8; j++) acc[i][j] = 0.f;

    const int kbeg = kc * 256, kend = kbeg + 256;
    for (int k0 = kbeg; k0 < kend; k0 += 16) {
        float4 xv = *(const float4*)(X + (size_t)lm * 1024 + k0 + lk);
        float4 w0 = *(const float4*)(W + (size_t)(k0 + lk2) * 1024 + n0 + ln);
        float4 w1 = *(const float4*)(W + (size_t)(k0 + lk2) * 1024 + n0 + ln + 4);
        __syncthreads();
        Xs[(lk + 0) * 64 + lm] = xv.x;
        Xs[(lk + 1) * 64 + lm] = xv.y;
        Xs[(lk + 2) * 64 + lm] = xv.z;
        Xs[(lk + 3) * 64 + lm] = xv.w;
        *(float4*)(Ws + lk2 * 128 + ln) = w0;
        *(float4*)(Ws + lk2 * 128 + ln + 4) = w1;
        __syncthreads();
#pragma unroll
        for (int kk = 0; kk < 16; kk++) {
            float4 a = *(const float4*)(Xs + kk * 64 + (ty << 2));
            float4 b0 = *(const float4*)(Ws + kk * 128 + (tx << 3));
            float4 b1 = *(const float4*)(Ws + kk * 128 + (tx << 3) + 4);
            float av[4] = {a.x, a.y, a.z, a.w};
            float bv[8] = {b0.x, b0.y, b0.z, b0.w, b1.x, b1.y, b1.z, b1.w};
#pragma unroll
            for (int i = 0; i < 4; i++)
#pragma unroll
                for (int j = 0; j < 8; j++) acc[i][j] += av[i] * bv[j];
        }
    }
    float* dst = g_qv1pre + z * 65536;
#pragma unroll
    for (int i = 0; i < 4; i++)
#pragma unroll
        for (int j = 0; j < 8; j++)
            atomicAdd(&dst[((ty << 2) + i) * 1024 + n0 + (tx << 3) + j], acc[i][j]);
}

__global__ void small_finalize(const float* __restrict__ bq, const float* __restrict__ gq,
                               const float* __restrict__ gbq,
                               const float* __restrict__ bv1, const float* __restrict__ gv1,
                               const float* __restrict__ gbv1) {
    const int row = blockIdx.x;
    const int z = row >> 6, r = row & 63;
    const int tid = threadIdx.x;
    const float* pre = g_qv1pre + z * 65536 + r * 1024;
    const float* bias = z ? bv1 : bq;
    const float* gam  = z ? gv1 : gq;
    const float* bet  = z ? gbv1 : gbq;
    float v[4], s = 0.f, s2 = 0.f;
#pragma unroll
    for (int j = 0; j < 4; j++) {
        int c = tid * 4 + j;
        float x = celu_f(pre[c] + bias[c]);
        v[j] = x; s += x; s2 += x * x;
    }
#pragma unroll
    for (int o = 16; o; o >>= 1) {
        s  += __shfl_xor_sync(0xffffffffu, s, o);
        s2 += __shfl_xor_sync(0xffffffffu, s2, o);
    }
    float mu = s * (1.f / 128.f);
    float var = s2 * (1.f / 128.f) - mu * mu;
    float rs = rsqrtf(var + EPS_F);
    float* o = z ? g_v1gn : g_qgn;
#pragma unroll
    for (int j = 0; j < 4; j++) {
        int c = tid * 4 + j;
        o[r * 1024 + c] = (v[j] - mu) * rs * gam[c] + bet[c];
    }
}

// ---------------------------------------------------------------------------
// fp16 mma.sync GEMM, cp.async 3-stage pipeline, 512 threads.
// D[128x128] = X[128 x 1024] @ W[1024 x 128], single fp16 term, fp32 accum.
// 16 warps (4/SMSP) 4m x 4n, warp tile 32x32. grid 4096 (512 m x 8 n).
// Epilogue: celu+GN; QMUL fuses attention (kq in Cs, am, logits, am_pool).
// smem: stages [0, 61440) = 3 x 20480 (A 10240 | B 10240, pitch 80B);
//       Cs [0, 67584) aliases stages post-loop;
//       qS 67584 | WbS 68096 | WlS 100864 | bbS 101120 | mS 101376 | apS 101888
// ---------------------------------------------------------------------------
#define STG_B 20480
#define SMQ_OFF  67584
#define SMWB_OFF (SMQ_OFF + 512)          // 68096
#define SMWL_OFF (SMWB_OFF + 32768)       // 100864
#define SMBB_OFF (SMWL_OFF + 256)         // 101120
#define SMMS_OFF (SMBB_OFF + 256)         // 101376
#define SMAP_OFF (SMMS_OFF + 512)         // 101888
#define SM_GEMM_TOTAL (SMAP_OFF + 256)    // 102144

template <bool QMUL>
__global__ void __launch_bounds__(512, 1)
gemm_kernel(const float* __restrict__ bias, const float* __restrict__ gam,
            const float* __restrict__ bet,
            const float* __restrict__ Wb, const float* __restrict__ bb,
            const float* __restrict__ Wl, const float* __restrict__ bl,
            const float* __restrict__ mask) {
    extern __shared__ char smem[];
    const uint32_t su = smem_to_u32(smem);
    const int tid = threadIdx.x, lane = tid & 31, wid = tid >> 5;
    const int mwarp = wid >> 2, nwarp = wid & 3;
    const int r0 = (int)(blockIdx.x >> 3) * 128;
    const int n0 = (int)(blockIdx.x & 7) * 128;
    const int b = r0 >> 10;
    const int g = (int)(blockIdx.x & 7);
    const int mbase = r0 & 1023;

    float* qS  = (float*)(smem + SMQ_OFF);
    float* WbS = (float*)(smem + SMWB_OFF);
    float* WlS = (float*)(smem + SMWL_OFF);
    float* bbS = (float*)(smem + SMBB_OFF);
    float* mS  = (float*)(smem + SMMS_OFF);
    float* apS = (float*)(smem + SMAP_OFF);

    if (QMUL) {
        for (int i = tid; i < 8192; i += 512) WbS[i] = Wb[i];
        if (tid < 128) {
            qS[tid] = g_qgn[b * 1024 + n0 + tid];
            mS[tid] = mask[r0 + tid];
        }
        if (tid < 64) {
            WlS[tid] = Wl[tid];
            bbS[tid] = bb[tid];
            apS[tid] = 0.f;
        }
    }

    const int rowL = (lane & 7) + ((lane >> 3) & 1) * 8;
    const int kL8 = (lane >> 4) * 8;
    const uint32_t lmoff = (uint32_t)(rowL * 80 + kL8 * 2);

    // staging: 512 threads, each copies one (row, 16B-seg) of A and of B
    const int srow = tid >> 2, sseg = tid & 3;
    const __half* Axh = g_xh + (size_t)(r0 + srow) * 1024 + sseg * 8;
    const __half* Bwh = g_wth + (size_t)(n0 + srow) * 1024 + sseg * 8;
    const uint32_t dA = su + srow * 80 + sseg * 16;

#define STAGE(s, c) do { \
    if ((c) < 32) { \
        const int _k0 = (c) << 5; \
        const uint32_t _d = dA + (s) * STG_B; \
        cp16(_d,         Axh + _k0); \
        cp16(_d + 10240, Bwh + _k0); \
    } \
    asm volatile("cp.async.commit_group;" ::: "memory"); \
} while (0)

    float d[2][4][4];
#pragma unroll
    for (int i = 0; i < 2; i++)
#pragma unroll
        for (int j = 0; j < 4; j++)
#pragma unroll
            for (int u = 0; u < 4; u++) d[i][j][u] = 0.f;

    STAGE(0, 0);
    STAGE(1, 1);

    for (int t = 0; t < 32; t++) {
        asm volatile("cp.async.wait_group 1;" ::: "memory");
        __syncthreads();            // data of buf t%3 visible; prev iter reads done
        STAGE((t + 2) % 3, t + 2);  // safe: buf (t+2)%3 last read at iter t-1

        const uint32_t abase = su + (t % 3) * STG_B +
                               (uint32_t)(mwarp * 32 * 80) + lmoff;
        const uint32_t bbase = su + (t % 3) * STG_B + 10240 +
                               (uint32_t)(nwarp * 32 * 80) + lmoff;
        // hoist all 8 ldsm ahead of all 16 mma
        uint32_t Ah[2][2][4], Bh[2][4][2];
#pragma unroll
        for (int sl = 0; sl < 2; sl++) {
#pragma unroll
            for (int fm = 0; fm < 2; fm++)
                ldsm4(Ah[sl][fm], abase + fm * (16 * 80) + sl * 32);
#pragma unroll
            for (int gg = 0; gg < 2; gg++) {
                uint32_t tm[4];
                ldsm4(tm, bbase + gg * (16 * 80) + sl * 32);
                Bh[sl][2 * gg][0] = tm[0]; Bh[sl][2 * gg][1] = tm[2];
                Bh[sl][2 * gg + 1][0] = tm[1]; Bh[sl][2 * gg + 1][1] = tm[3];
            }
        }
#pragma unroll
        for (int sl = 0; sl < 2; sl++)
#pragma unroll
            for (int fm = 0; fm < 2; fm++)
#pragma unroll
                for (int fn = 0; fn < 4; fn++)
                    mma16816(d[fm][fn], Ah[sl][fm], Bh[sl][fn][0], Bh[sl][fn][1]);
    }
    asm volatile("cp.async.wait_group 0;" ::: "memory");
    __syncthreads();   // all compute done before aliasing stage bufs as Cs

    // ---- epilogue: frags -> Cs (aliases stage bufs) ----
    float* Cs = (float*)smem;
    {
        const int mb = mwarp * 32, nb = nwarp * 32;
        const int r = lane >> 2, c = (lane & 3) * 2;
#pragma unroll
        for (int fm = 0; fm < 2; fm++)
#pragma unroll
            for (int fn = 0; fn < 4; fn++) {
                const int rr = mb + fm * 16 + r;
                const int cc = nb + fn * 8 + c;
                *(float2*)&Cs[rr * 132 + cc] = make_float2(d[fm][fn][0], d[fm][fn][1]);
                *(float2*)&Cs[(rr + 8) * 132 + cc] = make_float2(d[fm][fn][2], d[fm][fn][3]);
            }
    }
    __syncthreads();

    // ---- per-row bias + celu + GN; QMUL: kq back into Cs, else -> g_v2 ----
    {
        const int row = tid >> 2, q = tid & 3;
        const int c0 = q * 32;
        float v[32];
        float s = 0.f, s2 = 0.f;
#pragma unroll
        for (int j = 0; j < 8; j++) {
            float4 x4 = *(const float4*)&Cs[row * 132 + c0 + j * 4];
            float* px = (float*)&x4;
#pragma unroll
            for (int u = 0; u < 4; u++) {
                float x = celu_f(px[u] + __ldg(&bias[n0 + c0 + j * 4 + u]));
                v[j * 4 + u] = x; s += x; s2 += x * x;
            }
        }
        s  += __shfl_xor_sync(0xffffffffu, s, 1);
        s2 += __shfl_xor_sync(0xffffffffu, s2, 1);
        s  += __shfl_xor_sync(0xffffffffu, s, 2);
        s2 += __shfl_xor_sync(0xffffffffu, s2, 2);
        const float mu = s * (1.f / 128.f);
        const float rs = rsqrtf(s2 * (1.f / 128.f) - mu * mu + EPS_F);
        if (QMUL) {
#pragma unroll
            for (int j = 0; j < 8; j++) {
                float4 o;
                float* po = (float*)&o;
#pragma unroll
                for (int u = 0; u < 4; u++) {
                    const int ch = n0 + c0 + j * 4 + u;
                    float xn = (v[j * 4 + u] - mu) * rs * __ldg(&gam[ch]) + __ldg(&bet[ch]);
                    po[u] = xn * qS[c0 + j * 4 + u];
                }
                *(float4*)&Cs[row * 132 + c0 + j * 4] = o;
            }
        } else {
            float* outp = g_v2 + (size_t)(r0 + row) * 1024 + n0 + c0;
#pragma unroll
            for (int j = 0; j < 8; j++) {
                float4 o;
                float* po = (float*)&o;
#pragma unroll
                for (int u = 0; u < 4; u++) {
                    const int ch = n0 + c0 + j * 4 + u;
                    po[u] = (v[j * 4 + u] - mu) * rs * __ldg(&gam[ch]) + __ldg(&bet[ch]);
                }
                *(float4*)(outp + j * 4) = o;
            }
        }
    }

    // ---- fused attention stage (QMUL only): am, logits, am_pool ----
    if (QMUL) {
        __syncthreads();  // Cs now holds kq for the full 128x128 head tile
        const int ty = tid >> 4, tx = tid & 15;   // 32 x 16; thread tile 4x4

        float am[4][4];
#pragma unroll
        for (int i = 0; i < 4; i++)
#pragma unroll
            for (int j = 0; j < 4; j++) am[i][j] = 0.f;

        for (int k4 = 0; k4 < 128; k4 += 4) {
            float4 av[4];
#pragma unroll
            for (int i = 0; i < 4; i++)
                av[i] = *(const float4*)&Cs[((ty << 2) + i) * 132 + k4];
            float4 b0 = *(const float4*)(WbS + (k4 + 0) * 64 + (tx << 2));
            float4 b1 = *(const float4*)(WbS + (k4 + 1) * 64 + (tx << 2));
            float4 b2 = *(const float4*)(WbS + (k4 + 2) * 64 + (tx << 2));
            float4 b3 = *(const float4*)(WbS + (k4 + 3) * 64 + (tx << 2));
#pragma unroll
            for (int i = 0; i < 4; i++) {
                am[i][0] += av[i].x * b0.x; am[i][1] += av[i].x * b0.y;
                am[i][2] += av[i].x * b0.z; am[i][3] += av[i].x * b0.w;
                am[i][0] += av[i].y * b1.x; am[i][1] += av[i].y * b1.y;
                am[i][2] += av[i].y * b1.z; am[i][3] += av[i].y * b1.w;
                am[i][0] += av[i].z * b2.x; am[i][1] += av[i].z * b2.y;
                am[i][2] += av[i].z * b2.z; am[i][3] += av[i].z * b2.w;
                am[i][0] += av[i].w * b3.x; am[i][1] += av[i].w * b3.y;
                am[i][2] += av[i].w * b3.z; am[i][3] += av[i].w * b3.w;
            }
        }

        float lp[4];
#pragma unroll
        for (int i = 0; i < 4; i++) {
            float t = 0.f;
#pragma unroll
            for (int j = 0; j < 4; j++) {
                float a = fmaxf(am[i][j] + bbS[(tx << 2) + j], 0.f);
                am[i][j] = a;
                t += a * WlS[(tx << 2) + j];
            }
            lp[i] = t;
        }
#pragma unroll
        for (int o = 8; o; o >>= 1)
#pragma unroll
            for (int i = 0; i < 4; i++) lp[i] += __shfl_xor_sync(0xffffffffu, lp[i], o);
        if (tx == 0) {
            const float blv = __ldg(&bl[0]);
#pragma unroll
            for (int i = 0; i < 4; i++)
                g_logits[(((b << 3) + g) << 10) + mbase + (ty << 2) + i] = lp[i] + blv;
        }
#pragma unroll
        for (int j = 0; j < 4; j++) {
            float ap = am[0][j] * mS[(ty << 2) + 0] + am[1][j] * mS[(ty << 2) + 1] +
                       am[2][j] * mS[(ty << 2) + 2] + am[3][j] * mS[(ty << 2) + 3];
            atomicAdd(&apS[(tx << 2) + j], ap);
        }
        __syncthreads();
        if (tid < 64)
            atomicAdd(&g_ampool[(((b << 3) + g) << 6) + tid], apS[tid]);
    }
#undef STAGE
}

// ---------------- finalize ----------------
__global__ void final_kernel(const float* __restrict__ mask,
                             const float* __restrict__ Wl2,
                             const float* __restrict__ bl2,
                             float* __restrict__ out) {
    const int h = blockIdx.x, b = blockIdx.y;
    const int tid = threadIdx.x;
    const int lane = tid & 31, wrp = tid >> 5;
    __shared__ float wsm[1024];
    __shared__ float redA[8], redB[8], bc[4];
    __shared__ float pm[64], ac[128], psm[256];

    const float* lg = g_logits + (((size_t)b * 8 + h) << 10);
    const float* mrow = mask + ((size_t)b << 10);

    float l[4], mk[4];
    float lmax = -1e30f, msum = 0.f;
#pragma unroll
    for (int k = 0; k < 4; k++) {
        int m = tid + (k << 8);
        mk[k] = mrow[m];
        l[k] = (mk[k] == 0.f) ? -1e9f : lg[m];
        lmax = fmaxf(lmax, l[k]);
        msum += mk[k];
    }
#pragma unroll
    for (int o = 16; o; o >>= 1) {
        lmax = fmaxf(lmax, __shfl_xor_sync(0xffffffffu, lmax, o));
        msum += __shfl_xor_sync(0xffffffffu, msum, o);
    }
    if (lane == 0) { redA[wrp] = lmax; redB[wrp] = msum; }
    __syncthreads();
    if (tid == 0) {
        float a = -1e30f, s = 0.f;
#pragma unroll
        for (int i = 0; i < 8; i++) { a = fmaxf(a, redA[i]); s += redB[i]; }
        bc[0] = a; bc[1] = s;
    }
    __syncthreads();
    const float gmax = bc[0], msumv = bc[1];

    float es = 0.f;
#pragma unroll
    for (int k = 0; k < 4; k++) {
        float e = __expf(l[k] - gmax);
        wsm[tid + (k << 8)] = e;
        es += e;
    }
#pragma unroll
    for (int o = 16; o; o >>= 1) es += __shfl_xor_sync(0xffffffffu, es, o);
    if (lane == 0) redA[wrp] = es;
    __syncthreads();
    if (tid == 0) {
        float s = 0.f;
#pragma unroll
        for (int i = 0; i < 8; i++) s += redA[i];
        bc[2] = s;
    }
    if (tid < 64) pm[tid] = g_ampool[(((b << 3) + h) << 6) + tid] / msumv;
    __syncthreads();
    const float inv = 1.f / bc[2];

    if (tid < 128) {
        float t = bl2[tid];
#pragma unroll 8
        for (int n = 0; n < 64; n++) t += pm[n] * Wl2[n * 128 + tid];
        ac[tid] = 1.f / (1.f + __expf(-t));
    }
    __syncthreads();

    const int s2 = tid >> 7, d = tid & 127;
    const float* v2p = g_v2 + ((size_t)(b << 10)) * 1024 + (h << 7) + d;
    float accp = 0.f;
    for (int m = s2; m < 1024; m += 8) {
        accp += wsm[m] * v2p[(size_t)m * 1024];
        accp += wsm[m + 2] * v2p[(size_t)(m + 2) * 1024];
        accp += wsm[m + 4] * v2p[(size_t)(m + 4) * 1024];
        accp += wsm[m + 6] * v2p[(size_t)(m + 6) * 1024];
    }
    psm[tid] = accp;
    __syncthreads();
    if (tid < 128) {
        float p = (psm[tid] + psm[tid + 128]) * inv;
        int oi = (b << 10) + (h << 7) + tid;
        out[oi] = g_v1gn[oi] * p * ac[tid];
    }
}

// ---------------- launch ----------------
extern "C" void kernel_launch(void* const* d_in, const int* in_sizes, int n_in,
                              void* d_out, int out_size) {
    const float* query  = (const float*)d_in[0];
    const float* key    = (const float*)d_in[1];
    const float* mask   = (const float*)d_in[2];
    const float* value1 = (const float*)d_in[3];
    const float* value2 = (const float*)d_in[4];
    const float* Wq  = (const float*)d_in[5];
    const float* bq  = (const float*)d_in[6];
    const float* gq  = (const float*)d_in[7];
    const float* gbq = (const float*)d_in[8];
    const float* Wk  = (const float*)d_in[9];
    const float* bk  = (const float*)d_in[10];
    const float* gk  = (const float*)d_in[11];
    const float* gbk = (const float*)d_in[12];
    const float* Wv1  = (const float*)d_in[13];
    const float* bv1  = (const float*)d_in[14];
    const float* gv1  = (const float*)d_in[15];
    const float* gbv1 = (const float*)d_in[16];
    const float* Wv2  = (const float*)d_in[17];
    const float* bv2  = (const float*)d_in[18];
    const float* gv2  = (const float*)d_in[19];
    const float* gbv2 = (const float*)d_in[20];
    const float* Wb  = (const float*)d_in[21];
    const float* bb  = (const float*)d_in[22];
    const float* Wl  = (const float*)d_in[23];
    const float* bl  = (const float*)d_in[24];
    const float* Wl2 = (const float*)d_in[25];
    const float* bl2 = (const float*)d_in[26];
    float* out = (float*)d_out;

    cudaFuncSetAttribute(gemm_kernel<true>,  cudaFuncAttributeMaxDynamicSharedMemorySize,
                         SM_GEMM_TOTAL);
    cudaFuncSetAttribute(gemm_kernel<false>, cudaFuncAttributeMaxDynamicSharedMemorySize,
                         SM_GEMM_TOTAL);

    zero_kernel<<<512, 256>>>();
    small_partial<<<dim3(8, 4, 2), 256>>>(query, value1, Wq, Wv1);
    small_finalize<<<128, 256>>>(bq, gq, gbq, bv1, gv1, gbv1);

    // k branch (fused attention epilogue)
    convert_x<<<65536, 256>>>(key);
    convert_w<<<dim3(32, 32), 256>>>(Wk);
    gemm_kernel<true><<<4096, 512, SM_GEMM_TOTAL>>>(bk, gk, gbk, Wb, bb, Wl, bl, mask);

    // v2 branch (reuses conversion buffers)
    convert_x<<<65536, 256>>>(value2);
    convert_w<<<dim3(32, 32), 256>>>(Wv2);
    gemm_kernel<false><<<4096, 512, SM_GEMM_TOTAL>>>(bv2, gv2, gbv2,
                                                     nullptr, nullptr, nullptr, nullptr, nullptr);

    final_kernel<<<dim3(8, 64), 256>>>(mask, Wl2, bl2, out);
}